// round 3
// baseline (speedup 1.0000x reference)
#include <cuda_runtime.h>
#include <cuda_bf16.h>
#include <math_constants.h>

// Problem constants
#define D_MODEL   2048
#define N_HEADS   16
#define N_KV      4
#define DH        128
#define GROUPS    4
#define B_        2
#define T_        2048
#define QKV_DIM   3072          // 2048 + 2*4*128
#define ROWS      (B_*T_)       // 4096

// Scratch (static device allocations are allowed; runtime allocs are not)
__device__ float g_qkv[ROWS * QKV_DIM];   // 48 MB
__device__ float g_y  [ROWS * D_MODEL];   // 32 MB

// ---------------------------------------------------------------------------
// SGEMM: C[M,N] = A[M,K] @ B[K,N], all row-major fp32.
// 128x128 block, BK=8, 256 threads, 8x8 register tile per thread.
// ---------------------------------------------------------------------------
#define GBM 128
#define GBN 128
#define GBK 8

__global__ __launch_bounds__(256) void sgemm128(const float* __restrict__ A,
                                                const float* __restrict__ B,
                                                float* __restrict__ C,
                                                int M, int N, int K) {
    __shared__ float As[GBK][GBM];   // A stored transposed: As[k][m]
    __shared__ float Bs[GBK][GBN];

    const int tid = threadIdx.x;
    const int tx = tid & 15;         // 0..15 -> column group
    const int ty = tid >> 4;         // 0..15 -> row group
    const int bx = blockIdx.x, by = blockIdx.y;

    const int cRow = by * GBM + ty * 8;
    const int cCol = bx * GBN + tx * 8;

    // A tile load mapping: 128 rows x 8 cols, one float4 per thread
    const int aRow = tid >> 1;             // 0..127
    const int aCol = (tid & 1) * 4;        // 0 or 4
    // B tile load mapping: 8 rows x 128 cols, one float4 per thread
    const int bRow = tid >> 5;             // 0..7
    const int bCol = (tid & 31) * 4;       // 0..124

    const float* Aptr = A + (by * GBM + aRow) * K + aCol;
    const float* Bptr = B + bRow * N + bx * GBN + bCol;

    float acc[8][8];
#pragma unroll
    for (int i = 0; i < 8; i++)
#pragma unroll
        for (int j = 0; j < 8; j++) acc[i][j] = 0.f;

    for (int kt = 0; kt < K; kt += GBK) {
        float4 av = *(const float4*)(Aptr + kt);
        float4 bv = *(const float4*)(Bptr + (size_t)kt * N);
        As[aCol + 0][aRow] = av.x;
        As[aCol + 1][aRow] = av.y;
        As[aCol + 2][aRow] = av.z;
        As[aCol + 3][aRow] = av.w;
        *(float4*)&Bs[bRow][bCol] = bv;
        __syncthreads();

#pragma unroll
        for (int k = 0; k < GBK; k++) {
            float regA[8], regB[8];
            *(float4*)&regA[0] = *(const float4*)&As[k][ty * 8];
            *(float4*)&regA[4] = *(const float4*)&As[k][ty * 8 + 4];
            *(float4*)&regB[0] = *(const float4*)&Bs[k][tx * 8];
            *(float4*)&regB[4] = *(const float4*)&Bs[k][tx * 8 + 4];
#pragma unroll
            for (int i = 0; i < 8; i++)
#pragma unroll
                for (int j = 0; j < 8; j++)
                    acc[i][j] = fmaf(regA[i], regB[j], acc[i][j]);
        }
        __syncthreads();
    }

#pragma unroll
    for (int i = 0; i < 8; i++) {
        float4 v0 = make_float4(acc[i][0], acc[i][1], acc[i][2], acc[i][3]);
        float4 v1 = make_float4(acc[i][4], acc[i][5], acc[i][6], acc[i][7]);
        *(float4*)&C[(size_t)(cRow + i) * N + cCol]     = v0;
        *(float4*)&C[(size_t)(cRow + i) * N + cCol + 4] = v1;
    }
}

// ---------------------------------------------------------------------------
// RoPE, applied in place to the q and k portions of the qkv buffer.
// One thread per (even, odd) pair.
//   q pairs: B*T * (2048/2) = 4,194,304
//   k pairs: B*T * (512/2)  = 1,048,576
// ---------------------------------------------------------------------------
#define Q_PAIRS (ROWS * (D_MODEL / 2))            // 4194304
#define K_PAIRS (ROWS * (N_KV * DH / 2))          // 1048576

__global__ __launch_bounds__(256) void rope_kernel(float* __restrict__ qkv,
                                                   const int* __restrict__ start_pos) {
    int p = blockIdx.x * blockDim.x + threadIdx.x;
    if (p >= Q_PAIRS + K_PAIRS) return;

    int row, colbase, i;
    if (p < Q_PAIRS) {
        row = p >> 10;                 // / 1024 pairs per row in q region
        int rem = p & 1023;
        int h = rem >> 6;              // 0..15
        i = rem & 63;                  // 0..63
        colbase = h * DH + 2 * i;
    } else {
        int p2 = p - Q_PAIRS;
        row = p2 >> 8;                 // / 256 pairs per row in k region
        int rem = p2 & 255;
        int h = rem >> 6;              // 0..3
        i = rem & 63;
        colbase = D_MODEL + h * DH + 2 * i;
    }
    int t = row & (T_ - 1);
    float pos = (float)(start_pos[0] + t);
    // inv = 10000^(-i/64)
    float inv = exp2f(-(float)i * (13.287712379549449f / 64.0f));
    float ang = pos * inv;
    float s, c;
    sincosf(ang, &s, &c);

    size_t base = (size_t)row * QKV_DIM + colbase;
    float e = qkv[base];
    float o = qkv[base + 1];
    qkv[base]     = e * c - o * s;
    qkv[base + 1] = e * s + o * c;
}

// ---------------------------------------------------------------------------
// Flash attention (causal, GQA): one block per (q-tile of 64, head, batch).
// 256 threads: 4 threads per q-row (quad). Online softmax.
// smem: Q[64][128] K[64][128] V[64][128] S[64][64]  = 112 KB dynamic
// ---------------------------------------------------------------------------
#define FBM 64
#define FBN 64
#define FLASH_SMEM ((3 * FBM * DH + FBM * FBN) * 4)   // 114688 bytes

__global__ __launch_bounds__(256) void flash_kernel(const float* __restrict__ qkv,
                                                    float* __restrict__ y) {
    extern __shared__ float sm[];
    float* Qs = sm;                         // [64][128]
    float* Ks = sm + FBM * DH;              // [64][128]
    float* Vs = Ks + FBN * DH;              // [64][128]
    float* Ss = Vs + FBN * DH;              // [64][64]

    const int qb = blockIdx.x;
    const int h  = blockIdx.y;
    const int b  = blockIdx.z;
    const int kvh = h >> 2;                 // GQA group

    const int tid  = threadIdx.x;
    const int r    = tid >> 2;              // q row within tile, 0..63
    const int quad = tid & 3;
    const int dcol = quad * 32;             // output column slice
    const int qrow0 = qb * FBM;
    const float scale = 0.08838834764831845f;  // 1/sqrt(128)

    // Load Q tile (8192 floats, 8 float4 per thread, coalesced)
#pragma unroll
    for (int it = 0; it < 8; it++) {
        int f = it * 1024 + tid * 4;
        int row = f >> 7, col = f & 127;
        *(float4*)&Qs[f] = *(const float4*)&qkv[(size_t)(b * T_ + qrow0 + row) * QKV_DIM + h * DH + col];
    }

    float m = -CUDART_INF_F, l = 0.f;
    float acc[32];
#pragma unroll
    for (int i = 0; i < 32; i++) acc[i] = 0.f;

    for (int kb = 0; kb <= qb; kb++) {
        __syncthreads();   // previous iteration's smem reads done (also covers Q load on iter 0)
        // Load K and V tiles
#pragma unroll
        for (int it = 0; it < 8; it++) {
            int f = it * 1024 + tid * 4;
            int row = f >> 7, col = f & 127;
            size_t gbase = (size_t)(b * T_ + kb * FBN + row) * QKV_DIM;
            *(float4*)&Ks[f] = *(const float4*)&qkv[gbase + D_MODEL + kvh * DH + col];
            *(float4*)&Vs[f] = *(const float4*)&qkv[gbase + D_MODEL + N_KV * DH + kvh * DH + col];
        }
        __syncthreads();

        // S = Q K^T for this thread's 16 columns
        float s[16];
#pragma unroll
        for (int j = 0; j < 16; j++) s[j] = 0.f;
        const float* qrow = &Qs[r * DH];
        const float* kbase = &Ks[(quad * 16) * DH];
#pragma unroll 4
        for (int d4 = 0; d4 < 32; d4++) {
            float4 qv = *(const float4*)&qrow[d4 * 4];
#pragma unroll
            for (int j = 0; j < 16; j++) {
                float4 kv = *(const float4*)&kbase[j * DH + d4 * 4];
                s[j] = fmaf(qv.x, kv.x, s[j]);
                s[j] = fmaf(qv.y, kv.y, s[j]);
                s[j] = fmaf(qv.z, kv.z, s[j]);
                s[j] = fmaf(qv.w, kv.w, s[j]);
            }
        }

        // scale + causal mask + row max over this quad's 16 cols
        const int qg = qrow0 + r;
        const int kg0 = kb * FBN + quad * 16;
        float mloc = -CUDART_INF_F;
#pragma unroll
        for (int j = 0; j < 16; j++) {
            s[j] *= scale;
            if (kg0 + j > qg) s[j] = -CUDART_INF_F;
            mloc = fmaxf(mloc, s[j]);
        }
        // reduce max across the 4 threads of this row
        mloc = fmaxf(mloc, __shfl_xor_sync(0xffffffffu, mloc, 1));
        mloc = fmaxf(mloc, __shfl_xor_sync(0xffffffffu, mloc, 2));
        float mnew = fmaxf(m, mloc);
        float alpha = expf(m - mnew);

        float ls = 0.f;
#pragma unroll
        for (int j = 0; j < 16; j++) {
            float pj = expf(s[j] - mnew);
            Ss[r * FBN + quad * 16 + j] = pj;
            ls += pj;
        }
        ls += __shfl_xor_sync(0xffffffffu, ls, 1);
        ls += __shfl_xor_sync(0xffffffffu, ls, 2);
        l = l * alpha + ls;
        m = mnew;

#pragma unroll
        for (int i = 0; i < 32; i++) acc[i] *= alpha;

        __syncwarp();   // Ss[r][*] written by this thread's quad (same warp)

        // O += P @ V  (this thread: row r, cols dcol..dcol+31)
#pragma unroll 4
        for (int k = 0; k < FBN; k++) {
            float pk = Ss[r * FBN + k];
            const float* vrow = &Vs[k * DH + dcol];
#pragma unroll
            for (int i4 = 0; i4 < 8; i4++) {
                float4 vv = *(const float4*)&vrow[i4 * 4];
                acc[i4 * 4 + 0] = fmaf(pk, vv.x, acc[i4 * 4 + 0]);
                acc[i4 * 4 + 1] = fmaf(pk, vv.y, acc[i4 * 4 + 1]);
                acc[i4 * 4 + 2] = fmaf(pk, vv.z, acc[i4 * 4 + 2]);
                acc[i4 * 4 + 3] = fmaf(pk, vv.w, acc[i4 * 4 + 3]);
            }
        }
    }

    // normalize and write to y: [b, t, h*128 + d]
    float inv_l = 1.f / l;
    float* yout = &y[(size_t)(b * T_ + qrow0 + r) * D_MODEL + h * DH + dcol];
#pragma unroll
    for (int i4 = 0; i4 < 8; i4++) {
        float4 v = make_float4(acc[i4 * 4 + 0] * inv_l, acc[i4 * 4 + 1] * inv_l,
                               acc[i4 * 4 + 2] * inv_l, acc[i4 * 4 + 3] * inv_l);
        *(float4*)&yout[i4 * 4] = v;
    }
}

// ---------------------------------------------------------------------------
// Launch
// ---------------------------------------------------------------------------
extern "C" void kernel_launch(void* const* d_in, const int* in_sizes, int n_in,
                              void* d_out, int out_size) {
    const float* x        = (const float*)d_in[0];   // (2, 2048, 2048)
    const float* Wqkv     = (const float*)d_in[1];   // (2048, 3072)
    const float* Wo       = (const float*)d_in[2];   // (2048, 2048)
    const int*   startpos = (const int*)d_in[3];     // scalar
    float* out = (float*)d_out;                      // (2, 2048, 2048)

    float *qkv, *y;
    cudaGetSymbolAddress((void**)&qkv, g_qkv);
    cudaGetSymbolAddress((void**)&y, g_y);

    cudaFuncSetAttribute(flash_kernel, cudaFuncAttributeMaxDynamicSharedMemorySize, FLASH_SMEM);

    // 1) qkv = x @ Wqkv : (4096,3072) = (4096,2048)@(2048,3072)
    dim3 g1(QKV_DIM / GBN, ROWS / GBM);
    sgemm128<<<g1, 256>>>(x, Wqkv, qkv, ROWS, QKV_DIM, D_MODEL);

    // 2) RoPE in-place on q,k
    int total_pairs = Q_PAIRS + K_PAIRS;
    rope_kernel<<<(total_pairs + 255) / 256, 256>>>(qkv, startpos);

    // 3) flash attention -> y
    dim3 g3(T_ / FBM, N_HEADS, B_);
    flash_kernel<<<g3, 256, FLASH_SMEM>>>(qkv, y);

    // 4) out = y @ Wo : (4096,2048) = (4096,2048)@(2048,2048)
    dim3 g4(D_MODEL / GBN, ROWS / GBM);
    sgemm128<<<g4, 256>>>(y, Wo, out, ROWS, D_MODEL, D_MODEL);
}

// round 4
// speedup vs baseline: 9.5145x; 9.5145x over previous
#include <cuda_runtime.h>
#include <cuda_bf16.h>
#include <math_constants.h>

// Problem constants
#define D_MODEL   2048
#define N_HEADS   16
#define N_KV      4
#define DH        128
#define B_        2
#define T_        2048
#define QKV_DIM   3072          // 2048 + 2*4*128
#define ROWS      (B_*T_)       // 4096

// Scratch
__device__ float g_qkv[ROWS * QKV_DIM];   // 48 MB
__device__ float g_y  [ROWS * D_MODEL];   // 32 MB

// ---------------------------------------------------------------------------
// helpers: tf32 mma.sync
// ---------------------------------------------------------------------------
__device__ __forceinline__ unsigned f2tf(float x) {
    unsigned u;
    asm("cvt.rna.tf32.f32 %0, %1;" : "=r"(u) : "f"(x));
    return u;
}

__device__ __forceinline__ void mma8(float c[4], const unsigned a[4],
                                     unsigned b0, unsigned b1) {
    asm volatile(
        "mma.sync.aligned.m16n8k8.row.col.f32.tf32.tf32.f32 "
        "{%0,%1,%2,%3},{%4,%5,%6,%7},{%8,%9},{%0,%1,%2,%3};"
        : "+f"(c[0]), "+f"(c[1]), "+f"(c[2]), "+f"(c[3])
        : "r"(a[0]), "r"(a[1]), "r"(a[2]), "r"(a[3]), "r"(b0), "r"(b1));
}

#define CPA16(dst_u32, src_ptr) \
    asm volatile("cp.async.cg.shared.global [%0], [%1], 16;" :: "r"(dst_u32), "l"(src_ptr))
#define CPA_COMMIT() asm volatile("cp.async.commit_group;")
#define CPA_WAIT0()  asm volatile("cp.async.wait_group 0;")

// ---------------------------------------------------------------------------
// tf32 GEMM: C[M,N] = A[M,K] @ B[K,N] (row-major fp32 in/out)
// 128x128 block, BK=32, 256 threads (8 warps, warp tile 64x32),
// cp.async double-buffered smem. Padded strides: As 36, Bs 132 (conflict-free).
// ---------------------------------------------------------------------------
#define GAS 36
#define GBS 132
#define ASTAGE (128*GAS)
#define BSTAGE (32*GBS)
#define GEMM_SMEM ((2*(ASTAGE + BSTAGE)) * 4)   // 70656 bytes

__global__ __launch_bounds__(256) void gemm_tf32(const float* __restrict__ A,
                                                 const float* __restrict__ Bm,
                                                 float* __restrict__ C,
                                                 int M, int N, int K) {
    extern __shared__ float sm[];
    float* As = sm;
    float* Bs = sm + 2 * ASTAGE;
    const unsigned sm_u = (unsigned)__cvta_generic_to_shared(sm);
    const unsigned AsU = sm_u;
    const unsigned BsU = sm_u + 2 * ASTAGE * 4;

    const int tid = threadIdx.x;
    const int wid = tid >> 5, lane = tid & 31;
    const int g = lane >> 2, t = lane & 3;
    const int warp_m = (wid >> 2) * 64;
    const int warp_n = (wid & 3) * 32;
    const int bx = blockIdx.x, by = blockIdx.y;

    // global->smem mapping
    const int arow = tid >> 3;           // 0..31 (4 passes of 32 rows)
    const int acol = (tid & 7) * 4;      // 0..28
    const int brow = tid >> 5;           // 0..7  (4 passes of 8 rows)
    const int bcol = (tid & 31) * 4;     // 0..124

    const int nst = K / 32;

    float acc[4][4][4];
#pragma unroll
    for (int i = 0; i < 4; i++)
#pragma unroll
        for (int j = 0; j < 4; j++)
#pragma unroll
            for (int k = 0; k < 4; k++) acc[i][j][k] = 0.f;

    // prologue: issue tile 0
    {
#pragma unroll
        for (int p = 0; p < 4; p++)
            CPA16(AsU + ((arow + p * 32) * GAS + acol) * 4,
                  A + (size_t)(by * 128 + arow + p * 32) * K + acol);
#pragma unroll
        for (int p = 0; p < 4; p++)
            CPA16(BsU + ((brow + p * 8) * GBS + bcol) * 4,
                  Bm + (size_t)(brow + p * 8) * N + bx * 128 + bcol);
        CPA_COMMIT();
    }

    for (int kt = 0; kt < nst; kt++) {
        CPA_WAIT0();
        __syncthreads();

        if (kt + 1 < nst) {
            const int stg = (kt + 1) & 1;
            const int k0 = (kt + 1) * 32;
#pragma unroll
            for (int p = 0; p < 4; p++)
                CPA16(AsU + (stg * ASTAGE + (arow + p * 32) * GAS + acol) * 4,
                      A + (size_t)(by * 128 + arow + p * 32) * K + k0 + acol);
#pragma unroll
            for (int p = 0; p < 4; p++)
                CPA16(BsU + (stg * BSTAGE + (brow + p * 8) * GBS + bcol) * 4,
                      Bm + (size_t)(k0 + brow + p * 8) * N + bx * 128 + bcol);
            CPA_COMMIT();
        }

        const float* Ab = As + (kt & 1) * ASTAGE;
        const float* Bb = Bs + (kt & 1) * BSTAGE;

#pragma unroll
        for (int kk = 0; kk < 4; kk++) {
            unsigned af[4][4], bf[4][2];
#pragma unroll
            for (int mt = 0; mt < 4; mt++) {
                const int r = warp_m + mt * 16;
                af[mt][0] = f2tf(Ab[(r + g) * GAS + kk * 8 + t]);
                af[mt][1] = f2tf(Ab[(r + 8 + g) * GAS + kk * 8 + t]);
                af[mt][2] = f2tf(Ab[(r + g) * GAS + kk * 8 + t + 4]);
                af[mt][3] = f2tf(Ab[(r + 8 + g) * GAS + kk * 8 + t + 4]);
            }
#pragma unroll
            for (int nt = 0; nt < 4; nt++) {
                const int c = warp_n + nt * 8 + g;
                bf[nt][0] = f2tf(Bb[(kk * 8 + t) * GBS + c]);
                bf[nt][1] = f2tf(Bb[(kk * 8 + t + 4) * GBS + c]);
            }
#pragma unroll
            for (int mt = 0; mt < 4; mt++)
#pragma unroll
                for (int nt = 0; nt < 4; nt++)
                    mma8(acc[mt][nt], af[mt], bf[nt][0], bf[nt][1]);
        }
    }

    // epilogue
#pragma unroll
    for (int mt = 0; mt < 4; mt++) {
#pragma unroll
        for (int nt = 0; nt < 4; nt++) {
            const int r0 = by * 128 + warp_m + mt * 16 + g;
            const int c0 = bx * 128 + warp_n + nt * 8 + 2 * t;
            *(float2*)&C[(size_t)r0 * N + c0]       = make_float2(acc[mt][nt][0], acc[mt][nt][1]);
            *(float2*)&C[(size_t)(r0 + 8) * N + c0] = make_float2(acc[mt][nt][2], acc[mt][nt][3]);
        }
    }
}

// ---------------------------------------------------------------------------
// RoPE (unchanged)
// ---------------------------------------------------------------------------
#define Q_PAIRS (ROWS * (D_MODEL / 2))
#define K_PAIRS (ROWS * (N_KV * DH / 2))

__global__ __launch_bounds__(256) void rope_kernel(float* __restrict__ qkv,
                                                   const int* __restrict__ start_pos) {
    int p = blockIdx.x * blockDim.x + threadIdx.x;
    if (p >= Q_PAIRS + K_PAIRS) return;

    int row, colbase, i;
    if (p < Q_PAIRS) {
        row = p >> 10;
        int rem = p & 1023;
        int h = rem >> 6;
        i = rem & 63;
        colbase = h * DH + 2 * i;
    } else {
        int p2 = p - Q_PAIRS;
        row = p2 >> 8;
        int rem = p2 & 255;
        int h = rem >> 6;
        i = rem & 63;
        colbase = D_MODEL + h * DH + 2 * i;
    }
    int tpos = row & (T_ - 1);
    float pos = (float)(start_pos[0] + tpos);
    float inv = exp2f(-(float)i * (13.287712379549449f / 64.0f));
    float ang = pos * inv;
    float s, c;
    sincosf(ang, &s, &c);

    size_t base = (size_t)row * QKV_DIM + colbase;
    float e = qkv[base];
    float o = qkv[base + 1];
    qkv[base]     = e * c - o * s;
    qkv[base + 1] = e * s + o * c;
}

// ---------------------------------------------------------------------------
// Flash attention (causal, GQA) with tf32 mma.
// Block: 256 threads / 8 warps; q-tile 128 rows (16 per warp); kv-tile 64.
// smem: Qs[128][132] Ks[64][132] Vs[64][132] Ps[128][68]  (~166 KB)
// Q/K/V stored pre-converted to tf32 bit patterns.
// ---------------------------------------------------------------------------
#define FQS 132
#define FPS 68
#define FLASH_SMEM ((128*FQS + 64*FQS + 64*FQS + 128*FPS) * 4)   // 169984

__global__ __launch_bounds__(256) void flash_tf32(const float* __restrict__ qkv,
                                                  float* __restrict__ y) {
    extern __shared__ float sm[];
    float* Qs = sm;                    // [128][132]
    float* Ks = Qs + 128 * FQS;        // [64][132]
    float* Vs = Ks + 64 * FQS;         // [64][132]
    float* Ps = Vs + 64 * FQS;         // [128][68]

    const int tid = threadIdx.x;
    const int wid = tid >> 5, lane = tid & 31;
    const int g = lane >> 2, t = lane & 3;
    const int qb = blockIdx.x, h = blockIdx.y, b = blockIdx.z;
    const int kvh = h >> 2;
    const int q0 = wid * 16;
    // scale * log2(e): softmax computed in base-2
    const float SC = 0.08838834764831845f * 1.4426950408889634f;

    // load Q tile (convert to tf32 bits)
#pragma unroll
    for (int it = 0; it < 16; it++) {
        int f = it * 256 + tid;
        int row = f >> 5, col = (f & 31) * 4;
        float4 v = *(const float4*)&qkv[(size_t)(b * T_ + qb * 128 + row) * QKV_DIM + h * DH + col];
        float4 w = make_float4(__uint_as_float(f2tf(v.x)), __uint_as_float(f2tf(v.y)),
                               __uint_as_float(f2tf(v.z)), __uint_as_float(f2tf(v.w)));
        *(float4*)&Qs[row * FQS + col] = w;
    }

    float m_lo = -1e30f, m_hi = -1e30f, l_lo = 0.f, l_hi = 0.f;
    float o[16][4];
#pragma unroll
    for (int i = 0; i < 16; i++)
#pragma unroll
        for (int j = 0; j < 4; j++) o[i][j] = 0.f;

    const int ntiles = 2 * qb + 2;
    for (int kt = 0; kt < ntiles; kt++) {
        __syncthreads();   // previous tile's Ks/Vs reads done (covers Q store on iter 0)
        // load K,V tiles (convert to tf32 bits)
#pragma unroll
        for (int it = 0; it < 8; it++) {
            int f = it * 256 + tid;
            int row = f >> 5, col = (f & 31) * 4;
            size_t gb = (size_t)(b * T_ + kt * 64 + row) * QKV_DIM + D_MODEL + kvh * DH + col;
            float4 kv4 = *(const float4*)&qkv[gb];
            float4 vv4 = *(const float4*)&qkv[gb + N_KV * DH];
            *(float4*)&Ks[row * FQS + col] = make_float4(
                __uint_as_float(f2tf(kv4.x)), __uint_as_float(f2tf(kv4.y)),
                __uint_as_float(f2tf(kv4.z)), __uint_as_float(f2tf(kv4.w)));
            *(float4*)&Vs[row * FQS + col] = make_float4(
                __uint_as_float(f2tf(vv4.x)), __uint_as_float(f2tf(vv4.y)),
                __uint_as_float(f2tf(vv4.z)), __uint_as_float(f2tf(vv4.w)));
        }
        __syncthreads();

        // S = Q K^T  (per warp: m16 x n64, k=128)
        float s[8][4];
#pragma unroll
        for (int nt = 0; nt < 8; nt++)
#pragma unroll
            for (int j = 0; j < 4; j++) s[nt][j] = 0.f;

#pragma unroll
        for (int kk = 0; kk < 16; kk++) {
            unsigned a[4];
            a[0] = __float_as_uint(Qs[(q0 + g) * FQS + kk * 8 + t]);
            a[1] = __float_as_uint(Qs[(q0 + 8 + g) * FQS + kk * 8 + t]);
            a[2] = __float_as_uint(Qs[(q0 + g) * FQS + kk * 8 + t + 4]);
            a[3] = __float_as_uint(Qs[(q0 + 8 + g) * FQS + kk * 8 + t + 4]);
#pragma unroll
            for (int nt = 0; nt < 8; nt++) {
                unsigned b0 = __float_as_uint(Ks[(nt * 8 + g) * FQS + kk * 8 + t]);
                unsigned b1 = __float_as_uint(Ks[(nt * 8 + g) * FQS + kk * 8 + t + 4]);
                mma8(s[nt], a, b0, b1);
            }
        }

        // scale + causal mask + row max (rows g and g+8 tracked separately)
        const int rlo = qb * 128 + q0 + g;
        const int rhi = rlo + 8;
        const int cb = kt * 64;
        float ml = -1e30f, mh = -1e30f;
#pragma unroll
        for (int nt = 0; nt < 8; nt++) {
            const int c0 = cb + nt * 8 + 2 * t, c1 = c0 + 1;
            float x0 = s[nt][0] * SC; if (c0 > rlo) x0 = -1e30f;
            float x1 = s[nt][1] * SC; if (c1 > rlo) x1 = -1e30f;
            float x2 = s[nt][2] * SC; if (c0 > rhi) x2 = -1e30f;
            float x3 = s[nt][3] * SC; if (c1 > rhi) x3 = -1e30f;
            s[nt][0] = x0; s[nt][1] = x1; s[nt][2] = x2; s[nt][3] = x3;
            ml = fmaxf(ml, fmaxf(x0, x1));
            mh = fmaxf(mh, fmaxf(x2, x3));
        }
        ml = fmaxf(ml, __shfl_xor_sync(0xffffffffu, ml, 1));
        ml = fmaxf(ml, __shfl_xor_sync(0xffffffffu, ml, 2));
        mh = fmaxf(mh, __shfl_xor_sync(0xffffffffu, mh, 1));
        mh = fmaxf(mh, __shfl_xor_sync(0xffffffffu, mh, 2));

        const float mnl = fmaxf(m_lo, ml);
        const float mnh = fmaxf(m_hi, mh);
        const float al = exp2f(m_lo - mnl);
        const float ah = exp2f(m_hi - mnh);

        float ll = 0.f, lh = 0.f;
#pragma unroll
        for (int nt = 0; nt < 8; nt++) {
            float p0 = exp2f(s[nt][0] - mnl);
            float p1 = exp2f(s[nt][1] - mnl);
            float p2 = exp2f(s[nt][2] - mnh);
            float p3 = exp2f(s[nt][3] - mnh);
            ll += p0 + p1;
            lh += p2 + p3;
            Ps[(q0 + g) * FPS + nt * 8 + 2 * t]         = p0;
            Ps[(q0 + g) * FPS + nt * 8 + 2 * t + 1]     = p1;
            Ps[(q0 + 8 + g) * FPS + nt * 8 + 2 * t]     = p2;
            Ps[(q0 + 8 + g) * FPS + nt * 8 + 2 * t + 1] = p3;
        }
        ll += __shfl_xor_sync(0xffffffffu, ll, 1);
        ll += __shfl_xor_sync(0xffffffffu, ll, 2);
        lh += __shfl_xor_sync(0xffffffffu, lh, 1);
        lh += __shfl_xor_sync(0xffffffffu, lh, 2);

        l_lo = l_lo * al + ll;
        l_hi = l_hi * ah + lh;
        m_lo = mnl;
        m_hi = mnh;

#pragma unroll
        for (int nt = 0; nt < 16; nt++) {
            o[nt][0] *= al; o[nt][1] *= al;
            o[nt][2] *= ah; o[nt][3] *= ah;
        }
        __syncwarp();   // Ps rows written by this warp, read below by this warp

        // O += P @ V  (per warp: m16 x n128, k=64)
#pragma unroll
        for (int kk = 0; kk < 8; kk++) {
            unsigned a[4];
            a[0] = __float_as_uint(Ps[(q0 + g) * FPS + kk * 8 + t]);
            a[1] = __float_as_uint(Ps[(q0 + 8 + g) * FPS + kk * 8 + t]);
            a[2] = __float_as_uint(Ps[(q0 + g) * FPS + kk * 8 + t + 4]);
            a[3] = __float_as_uint(Ps[(q0 + 8 + g) * FPS + kk * 8 + t + 4]);
#pragma unroll
            for (int nt = 0; nt < 16; nt++) {
                unsigned b0 = __float_as_uint(Vs[(kk * 8 + t) * FQS + nt * 8 + g]);
                unsigned b1 = __float_as_uint(Vs[(kk * 8 + t + 4) * FQS + nt * 8 + g]);
                mma8(o[nt], a, b0, b1);
            }
        }
    }

    // epilogue: normalize + write y
    const float il = 1.f / l_lo;
    const float ih = 1.f / l_hi;
    const size_t rl = (size_t)(b * T_ + qb * 128 + q0 + g);
#pragma unroll
    for (int nt = 0; nt < 16; nt++) {
        const int c = h * DH + nt * 8 + 2 * t;
        *(float2*)&y[rl * D_MODEL + c]       = make_float2(o[nt][0] * il, o[nt][1] * il);
        *(float2*)&y[(rl + 8) * D_MODEL + c] = make_float2(o[nt][2] * ih, o[nt][3] * ih);
    }
}

// ---------------------------------------------------------------------------
// Launch
// ---------------------------------------------------------------------------
extern "C" void kernel_launch(void* const* d_in, const int* in_sizes, int n_in,
                              void* d_out, int out_size) {
    const float* x        = (const float*)d_in[0];   // (2, 2048, 2048)
    const float* Wqkv     = (const float*)d_in[1];   // (2048, 3072)
    const float* Wo       = (const float*)d_in[2];   // (2048, 2048)
    const int*   startpos = (const int*)d_in[3];     // scalar
    float* out = (float*)d_out;                      // (2, 2048, 2048)

    float *qkv, *y;
    cudaGetSymbolAddress((void**)&qkv, g_qkv);
    cudaGetSymbolAddress((void**)&y, g_y);

    cudaFuncSetAttribute(gemm_tf32, cudaFuncAttributeMaxDynamicSharedMemorySize, GEMM_SMEM);
    cudaFuncSetAttribute(flash_tf32, cudaFuncAttributeMaxDynamicSharedMemorySize, FLASH_SMEM);

    // 1) qkv = x @ Wqkv : (4096,3072)
    dim3 g1(QKV_DIM / 128, ROWS / 128);
    gemm_tf32<<<g1, 256, GEMM_SMEM>>>(x, Wqkv, qkv, ROWS, QKV_DIM, D_MODEL);

    // 2) RoPE in-place on q,k
    int total_pairs = Q_PAIRS + K_PAIRS;
    rope_kernel<<<(total_pairs + 255) / 256, 256>>>(qkv, startpos);

    // 3) flash attention -> y
    dim3 g3(T_ / 128, N_HEADS, B_);
    flash_tf32<<<g3, 256, FLASH_SMEM>>>(qkv, y);

    // 4) out = y @ Wo : (4096,2048)
    dim3 g4(D_MODEL / 128, ROWS / 128);
    gemm_tf32<<<g4, 256, GEMM_SMEM>>>(y, Wo, out, ROWS, D_MODEL, D_MODEL);
}

// round 5
// speedup vs baseline: 13.0053x; 1.3669x over previous
#include <cuda_runtime.h>
#include <cuda_bf16.h>
#include <math_constants.h>

// Problem constants
#define D_MODEL   2048
#define N_HEADS   16
#define N_KV      4
#define DH        128
#define B_        2
#define T_        2048
#define QKV_DIM   3072          // 2048 + 2*4*128
#define ROWS      (B_*T_)       // 4096

// Scratch (static device allocations only)
__device__ float  g_qkv [ROWS * QKV_DIM];     // 48 MB
__device__ float  g_y   [ROWS * D_MODEL];     // 32 MB
__device__ float  g_x   [ROWS * D_MODEL];     // 32 MB  (tf32-rounded x)
__device__ float  g_wq  [D_MODEL * QKV_DIM];  // 24 MB  (tf32-rounded Wqkv)
__device__ float  g_wo  [D_MODEL * D_MODEL];  // 16 MB  (tf32-rounded Wo)
__device__ float2 g_rtab[T_ * 64];            // 1 MB   (cos/sin table)

// ---------------------------------------------------------------------------
// helpers
// ---------------------------------------------------------------------------
__device__ __forceinline__ unsigned f2tf(float x) {
    unsigned u;
    asm("cvt.rna.tf32.f32 %0, %1;" : "=r"(u) : "f"(x));
    return u;
}
__device__ __forceinline__ float rtf(float x) { return __uint_as_float(f2tf(x)); }

__device__ __forceinline__ void mma8(float c[4], const unsigned a[4],
                                     unsigned b0, unsigned b1) {
    asm volatile(
        "mma.sync.aligned.m16n8k8.row.col.f32.tf32.tf32.f32 "
        "{%0,%1,%2,%3},{%4,%5,%6,%7},{%8,%9},{%0,%1,%2,%3};"
        : "+f"(c[0]), "+f"(c[1]), "+f"(c[2]), "+f"(c[3])
        : "r"(a[0]), "r"(a[1]), "r"(a[2]), "r"(a[3]), "r"(b0), "r"(b1));
}

#define CPA16(dst_u32, src_ptr) \
    asm volatile("cp.async.cg.shared.global [%0], [%1], 16;" :: "r"(dst_u32), "l"(src_ptr))
#define CPA_COMMIT() asm volatile("cp.async.commit_group;")
#define CPA_WAIT(n)  asm volatile("cp.async.wait_group %0;" :: "n"(n))

// ---------------------------------------------------------------------------
// elementwise tf32 pre-rounding
// ---------------------------------------------------------------------------
__global__ __launch_bounds__(256) void round_tf32_kernel(const float* __restrict__ in,
                                                         float* __restrict__ out, int n4) {
    int i = blockIdx.x * 256 + threadIdx.x;
    if (i >= n4) return;
    float4 v = ((const float4*)in)[i];
    ((float4*)out)[i] = make_float4(rtf(v.x), rtf(v.y), rtf(v.z), rtf(v.w));
}

// ---------------------------------------------------------------------------
// rope table: cos/sin for (t, i)
// ---------------------------------------------------------------------------
__global__ __launch_bounds__(256) void rope_table_kernel(const int* __restrict__ start_pos) {
    int id = blockIdx.x * 256 + threadIdx.x;    // < 2048*64
    int t = id >> 6, i = id & 63;
    float pos = (float)(start_pos[0] + t);
    float inv = exp2f(-(float)i * (13.287712379549449f / 64.0f));
    float ang = pos * inv;
    float s, c;
    sincosf(ang, &s, &c);
    g_rtab[id] = make_float2(c, s);
}

// ---------------------------------------------------------------------------
// RoPE (q,k) + tf32 rounding of the whole qkv buffer (q,k,v).
// One block per row (4096 blocks), 3 float4 per thread.
// ---------------------------------------------------------------------------
__global__ __launch_bounds__(256) void rope_round_kernel(float* __restrict__ qkv) {
    const int row = blockIdx.x;
    const int t = row & (T_ - 1);
    const float2* tab = g_rtab + t * 64;
#pragma unroll
    for (int it = 0; it < 3; it++) {
        const int c = (threadIdx.x + it * 256) * 4;
        const size_t idx = (size_t)row * QKV_DIM + c;
        float4 v = *(float4*)&qkv[idx];
        if (c < 2560) {                      // q region [0,2048) or k region [2048,2560)
            const int i0 = (c & 127) >> 1;   // pair index within head
            float2 cs0 = tab[i0];
            float2 cs1 = tab[i0 + 1];
            float e0 = v.x * cs0.x - v.y * cs0.y;
            float o0 = v.x * cs0.y + v.y * cs0.x;
            float e1 = v.z * cs1.x - v.w * cs1.y;
            float o1 = v.z * cs1.y + v.w * cs1.x;
            v = make_float4(rtf(e0), rtf(o0), rtf(e1), rtf(o1));
        } else {                             // v region: round only
            v = make_float4(rtf(v.x), rtf(v.y), rtf(v.z), rtf(v.w));
        }
        *(float4*)&qkv[idx] = v;
    }
}

// ---------------------------------------------------------------------------
// tf32 GEMM: C[M,N] = A[M,K] @ B[K,N]; A,B pre-rounded to tf32 values.
// 128x128 block, BK=32, 256 threads (8 warps, warp tile 64x32),
// cp.async double-buffered. As stride 36, Bs stride 136 (both conflict-free).
// ---------------------------------------------------------------------------
#define GAS 36
#define GBS 136
#define ASTAGE (128*GAS)
#define BSTAGE (32*GBS)
#define GEMM_SMEM ((2*(ASTAGE + BSTAGE)) * 4)   // 71680 bytes

__global__ __launch_bounds__(256) void gemm_tf32(const float* __restrict__ A,
                                                 const float* __restrict__ Bm,
                                                 float* __restrict__ C,
                                                 int M, int N, int K) {
    extern __shared__ float sm[];
    float* As = sm;
    float* Bs = sm + 2 * ASTAGE;
    const unsigned sm_u = (unsigned)__cvta_generic_to_shared(sm);
    const unsigned AsU = sm_u;
    const unsigned BsU = sm_u + 2 * ASTAGE * 4;

    const int tid = threadIdx.x;
    const int wid = tid >> 5, lane = tid & 31;
    const int g = lane >> 2, t = lane & 3;
    const int warp_m = (wid >> 2) * 64;
    const int warp_n = (wid & 3) * 32;
    const int bx = blockIdx.x, by = blockIdx.y;

    const int arow = tid >> 3;           // 0..31 (4 passes of 32 rows)
    const int acol = (tid & 7) * 4;      // 0..28
    const int brow = tid >> 5;           // 0..7  (4 passes of 8 rows)
    const int bcol = (tid & 31) * 4;     // 0..124

    const int nst = K / 32;

    float acc[4][4][4];
#pragma unroll
    for (int i = 0; i < 4; i++)
#pragma unroll
        for (int j = 0; j < 4; j++)
#pragma unroll
            for (int k = 0; k < 4; k++) acc[i][j][k] = 0.f;

    {
#pragma unroll
        for (int p = 0; p < 4; p++)
            CPA16(AsU + ((arow + p * 32) * GAS + acol) * 4,
                  A + (size_t)(by * 128 + arow + p * 32) * K + acol);
#pragma unroll
        for (int p = 0; p < 4; p++)
            CPA16(BsU + ((brow + p * 8) * GBS + bcol) * 4,
                  Bm + (size_t)(brow + p * 8) * N + bx * 128 + bcol);
        CPA_COMMIT();
    }

    for (int kt = 0; kt < nst; kt++) {
        CPA_WAIT(0);
        __syncthreads();

        if (kt + 1 < nst) {
            const int stg = (kt + 1) & 1;
            const int k0 = (kt + 1) * 32;
#pragma unroll
            for (int p = 0; p < 4; p++)
                CPA16(AsU + (stg * ASTAGE + (arow + p * 32) * GAS + acol) * 4,
                      A + (size_t)(by * 128 + arow + p * 32) * K + k0 + acol);
#pragma unroll
            for (int p = 0; p < 4; p++)
                CPA16(BsU + (stg * BSTAGE + (brow + p * 8) * GBS + bcol) * 4,
                      Bm + (size_t)(k0 + brow + p * 8) * N + bx * 128 + bcol);
            CPA_COMMIT();
        }

        const float* Ab = As + (kt & 1) * ASTAGE;
        const float* Bb = Bs + (kt & 1) * BSTAGE;

#pragma unroll
        for (int kk = 0; kk < 4; kk++) {
            unsigned af[4][4], bf[4][2];
#pragma unroll
            for (int mt = 0; mt < 4; mt++) {
                const int r = warp_m + mt * 16;
                af[mt][0] = __float_as_uint(Ab[(r + g) * GAS + kk * 8 + t]);
                af[mt][1] = __float_as_uint(Ab[(r + 8 + g) * GAS + kk * 8 + t]);
                af[mt][2] = __float_as_uint(Ab[(r + g) * GAS + kk * 8 + t + 4]);
                af[mt][3] = __float_as_uint(Ab[(r + 8 + g) * GAS + kk * 8 + t + 4]);
            }
#pragma unroll
            for (int nt = 0; nt < 4; nt++) {
                const int c = warp_n + nt * 8 + g;
                bf[nt][0] = __float_as_uint(Bb[(kk * 8 + t) * GBS + c]);
                bf[nt][1] = __float_as_uint(Bb[(kk * 8 + t + 4) * GBS + c]);
            }
#pragma unroll
            for (int mt = 0; mt < 4; mt++)
#pragma unroll
                for (int nt = 0; nt < 4; nt++)
                    mma8(acc[mt][nt], af[mt], bf[nt][0], bf[nt][1]);
        }
    }

#pragma unroll
    for (int mt = 0; mt < 4; mt++) {
#pragma unroll
        for (int nt = 0; nt < 4; nt++) {
            const int r0 = by * 128 + warp_m + mt * 16 + g;
            const int c0 = bx * 128 + warp_n + nt * 8 + 2 * t;
            *(float2*)&C[(size_t)r0 * N + c0]       = make_float2(acc[mt][nt][0], acc[mt][nt][1]);
            *(float2*)&C[(size_t)(r0 + 8) * N + c0] = make_float2(acc[mt][nt][2], acc[mt][nt][3]);
        }
    }
}

// ---------------------------------------------------------------------------
// Flash attention (causal, GQA), tf32 mma, swizzled smem, cp.async dbuf.
// 256 threads / 8 warps; q-tile 128 (16 rows/warp); kv-tile 64.
// smem floats: Qs 128*128 | Ks 2*64*128 | Vs 2*64*128 | Ps 128*68
// Q/K swizzle: col ^ (4*(row&7)); V swizzle: col ^ (8*(row&3)).
// ---------------------------------------------------------------------------
#define FPS 68
#define Q_OFF 0
#define K_OFF 16384
#define V_OFF 32768
#define P_OFF 49152
#define FLASH_SMEM ((49152 + 128*FPS) * 4)   // 231424 bytes

#define SWQ(row, col) (((row) << 7) + ((col) ^ ((((row) & 7)) << 2)))
#define SWV(row, col) (((row) << 7) + ((col) ^ ((((row) & 3)) << 3)))

__global__ __launch_bounds__(256) void flash_tf32(const float* __restrict__ qkv,
                                                  float* __restrict__ y) {
    extern __shared__ float sm[];
    float* Qs = sm + Q_OFF;
    float* Ks = sm + K_OFF;
    float* Vs = sm + V_OFF;
    float* Ps = sm + P_OFF;
    const unsigned base_u = (unsigned)__cvta_generic_to_shared(sm);

    const int tid = threadIdx.x;
    const int wid = tid >> 5, lane = tid & 31;
    const int g = lane >> 2, t = lane & 3;
    const int qb = gridDim.x - 1 - blockIdx.x;   // long blocks first
    const int h = blockIdx.y, b = blockIdx.z;
    const int kvh = h >> 2;
    const int q0 = wid * 16;
    const float SC = 0.08838834764831845f * 1.4426950408889634f;  // scale*log2(e)

    const int ldrow = tid >> 5;          // 0..7 per pass
    const int ldc4 = (tid & 31) * 4;     // chunk column

    // Q tile via cp.async (group 0)
#pragma unroll
    for (int it = 0; it < 16; it++) {
        const int row = it * 8 + ldrow;
        CPA16(base_u + (Q_OFF + SWQ(row, ldc4)) * 4,
              qkv + (size_t)(b * T_ + qb * 128 + row) * QKV_DIM + h * DH + ldc4);
    }
    CPA_COMMIT();

    const int ntiles = 2 * qb + 2;

    // KV stage 0 (group 1)
    {
#pragma unroll
        for (int it = 0; it < 8; it++) {
            const int row = it * 8 + ldrow;
            const float* gp = qkv + (size_t)(b * T_ + row) * QKV_DIM + D_MODEL + kvh * DH + ldc4;
            CPA16(base_u + (K_OFF + SWQ(row, ldc4)) * 4, gp);
            CPA16(base_u + (V_OFF + SWV(row, ldc4)) * 4, gp + N_KV * DH);
        }
        CPA_COMMIT();
    }

    float m_lo = -1e30f, m_hi = -1e30f, l_lo = 0.f, l_hi = 0.f;
    float o[16][4];
#pragma unroll
    for (int i = 0; i < 16; i++)
#pragma unroll
        for (int j = 0; j < 4; j++) o[i][j] = 0.f;

    for (int kt = 0; kt < ntiles; kt++) {
        if (kt + 1 < ntiles) {
            const int stg = (kt + 1) & 1;
#pragma unroll
            for (int it = 0; it < 8; it++) {
                const int row = it * 8 + ldrow;
                const float* gp = qkv + (size_t)(b * T_ + (kt + 1) * 64 + row) * QKV_DIM
                                  + D_MODEL + kvh * DH + ldc4;
                CPA16(base_u + (K_OFF + stg * 8192 + SWQ(row, ldc4)) * 4, gp);
                CPA16(base_u + (V_OFF + stg * 8192 + SWV(row, ldc4)) * 4, gp + N_KV * DH);
            }
            CPA_COMMIT();
            CPA_WAIT(1);
        } else {
            CPA_WAIT(0);
        }
        __syncthreads();

        const float* Kb = Ks + (kt & 1) * 8192;
        const float* Vb = Vs + (kt & 1) * 8192;

        // S = Q K^T  (per warp: m16 x n64, k=128)
        float s[8][4];
#pragma unroll
        for (int nt = 0; nt < 8; nt++)
#pragma unroll
            for (int j = 0; j < 4; j++) s[nt][j] = 0.f;

#pragma unroll
        for (int kk = 0; kk < 16; kk++) {
            unsigned a[4];
            a[0] = __float_as_uint(Qs[SWQ(q0 + g,     kk * 8 + t)]);
            a[1] = __float_as_uint(Qs[SWQ(q0 + 8 + g, kk * 8 + t)]);
            a[2] = __float_as_uint(Qs[SWQ(q0 + g,     kk * 8 + t + 4)]);
            a[3] = __float_as_uint(Qs[SWQ(q0 + 8 + g, kk * 8 + t + 4)]);
#pragma unroll
            for (int nt = 0; nt < 8; nt++) {
                unsigned b0 = __float_as_uint(Kb[SWQ(nt * 8 + g, kk * 8 + t)]);
                unsigned b1 = __float_as_uint(Kb[SWQ(nt * 8 + g, kk * 8 + t + 4)]);
                mma8(s[nt], a, b0, b1);
            }
        }

        // scale + causal mask + row max
        const int rlo = qb * 128 + q0 + g;
        const int rhi = rlo + 8;
        const int cb = kt * 64;
        float ml = -1e30f, mh = -1e30f;
#pragma unroll
        for (int nt = 0; nt < 8; nt++) {
            const int c0 = cb + nt * 8 + 2 * t, c1 = c0 + 1;
            float x0 = s[nt][0] * SC; if (c0 > rlo) x0 = -1e30f;
            float x1 = s[nt][1] * SC; if (c1 > rlo) x1 = -1e30f;
            float x2 = s[nt][2] * SC; if (c0 > rhi) x2 = -1e30f;
            float x3 = s[nt][3] * SC; if (c1 > rhi) x3 = -1e30f;
            s[nt][0] = x0; s[nt][1] = x1; s[nt][2] = x2; s[nt][3] = x3;
            ml = fmaxf(ml, fmaxf(x0, x1));
            mh = fmaxf(mh, fmaxf(x2, x3));
        }
        ml = fmaxf(ml, __shfl_xor_sync(0xffffffffu, ml, 1));
        ml = fmaxf(ml, __shfl_xor_sync(0xffffffffu, ml, 2));
        mh = fmaxf(mh, __shfl_xor_sync(0xffffffffu, mh, 1));
        mh = fmaxf(mh, __shfl_xor_sync(0xffffffffu, mh, 2));

        const float mnl = fmaxf(m_lo, ml);
        const float mnh = fmaxf(m_hi, mh);
        const float al = exp2f(m_lo - mnl);
        const float ah = exp2f(m_hi - mnh);

        float ll = 0.f, lh = 0.f;
#pragma unroll
        for (int nt = 0; nt < 8; nt++) {
            float p0 = exp2f(s[nt][0] - mnl);
            float p1 = exp2f(s[nt][1] - mnl);
            float p2 = exp2f(s[nt][2] - mnh);
            float p3 = exp2f(s[nt][3] - mnh);
            ll += p0 + p1;
            lh += p2 + p3;
            *(float2*)&Ps[(q0 + g) * FPS + nt * 8 + 2 * t]     = make_float2(p0, p1);
            *(float2*)&Ps[(q0 + 8 + g) * FPS + nt * 8 + 2 * t] = make_float2(p2, p3);
        }
        ll += __shfl_xor_sync(0xffffffffu, ll, 1);
        ll += __shfl_xor_sync(0xffffffffu, ll, 2);
        lh += __shfl_xor_sync(0xffffffffu, lh, 1);
        lh += __shfl_xor_sync(0xffffffffu, lh, 2);

        l_lo = l_lo * al + ll;
        l_hi = l_hi * ah + lh;
        m_lo = mnl;
        m_hi = mnh;

#pragma unroll
        for (int nt = 0; nt < 16; nt++) {
            o[nt][0] *= al; o[nt][1] *= al;
            o[nt][2] *= ah; o[nt][3] *= ah;
        }
        __syncwarp();   // Ps rows are warp-private

        // O += P @ V  (per warp: m16 x n128, k=64)
#pragma unroll
        for (int kk = 0; kk < 8; kk++) {
            unsigned a[4];
            a[0] = __float_as_uint(Ps[(q0 + g) * FPS + kk * 8 + t]);
            a[1] = __float_as_uint(Ps[(q0 + 8 + g) * FPS + kk * 8 + t]);
            a[2] = __float_as_uint(Ps[(q0 + g) * FPS + kk * 8 + t + 4]);
            a[3] = __float_as_uint(Ps[(q0 + 8 + g) * FPS + kk * 8 + t + 4]);
#pragma unroll
            for (int nt = 0; nt < 16; nt++) {
                unsigned b0 = __float_as_uint(Vb[SWV(kk * 8 + t,     nt * 8 + g)]);
                unsigned b1 = __float_as_uint(Vb[SWV(kk * 8 + t + 4, nt * 8 + g)]);
                mma8(o[nt], a, b0, b1);
            }
        }
        __syncthreads();   // compute done before next iter overwrites the other stage
    }

    // epilogue: normalize, round to tf32 (out-GEMM reads raw), write y
    const float il = 1.f / l_lo;
    const float ih = 1.f / l_hi;
    const size_t rl = (size_t)(b * T_ + qb * 128 + q0 + g);
#pragma unroll
    for (int nt = 0; nt < 16; nt++) {
        const int c = h * DH + nt * 8 + 2 * t;
        *(float2*)&y[rl * D_MODEL + c]       = make_float2(rtf(o[nt][0] * il), rtf(o[nt][1] * il));
        *(float2*)&y[(rl + 8) * D_MODEL + c] = make_float2(rtf(o[nt][2] * ih), rtf(o[nt][3] * ih));
    }
}

// ---------------------------------------------------------------------------
// Launch
// ---------------------------------------------------------------------------
extern "C" void kernel_launch(void* const* d_in, const int* in_sizes, int n_in,
                              void* d_out, int out_size) {
    const float* x        = (const float*)d_in[0];   // (2, 2048, 2048)
    const float* Wqkv     = (const float*)d_in[1];   // (2048, 3072)
    const float* Wo       = (const float*)d_in[2];   // (2048, 2048)
    const int*   startpos = (const int*)d_in[3];     // scalar
    float* out = (float*)d_out;                      // (2, 2048, 2048)

    float *qkv, *y, *xr, *wq, *wo;
    cudaGetSymbolAddress((void**)&qkv, g_qkv);
    cudaGetSymbolAddress((void**)&y, g_y);
    cudaGetSymbolAddress((void**)&xr, g_x);
    cudaGetSymbolAddress((void**)&wq, g_wq);
    cudaGetSymbolAddress((void**)&wo, g_wo);

    cudaFuncSetAttribute(gemm_tf32, cudaFuncAttributeMaxDynamicSharedMemorySize, GEMM_SMEM);
    cudaFuncSetAttribute(flash_tf32, cudaFuncAttributeMaxDynamicSharedMemorySize, FLASH_SMEM);

    // 0) tf32 pre-rounding + rope table
    round_tf32_kernel<<<(ROWS * D_MODEL / 4 + 255) / 256, 256>>>(x, xr, ROWS * D_MODEL / 4);
    round_tf32_kernel<<<(D_MODEL * QKV_DIM / 4 + 255) / 256, 256>>>(Wqkv, wq, D_MODEL * QKV_DIM / 4);
    round_tf32_kernel<<<(D_MODEL * D_MODEL / 4 + 255) / 256, 256>>>(Wo, wo, D_MODEL * D_MODEL / 4);
    rope_table_kernel<<<T_ * 64 / 256, 256>>>(startpos);

    // 1) qkv = x @ Wqkv
    dim3 g1(QKV_DIM / 128, ROWS / 128);
    gemm_tf32<<<g1, 256, GEMM_SMEM>>>(xr, wq, qkv, ROWS, QKV_DIM, D_MODEL);

    // 2) RoPE + tf32 round (q,k,v)
    rope_round_kernel<<<ROWS, 256>>>(qkv);

    // 3) flash attention -> y (tf32-rounded)
    dim3 g3(T_ / 128, N_HEADS, B_);
    flash_tf32<<<g3, 256, FLASH_SMEM>>>(qkv, y);

    // 4) out = y @ Wo
    dim3 g4(D_MODEL / 128, ROWS / 128);
    gemm_tf32<<<g4, 256, GEMM_SMEM>>>(y, wo, out, ROWS, D_MODEL, D_MODEL);
}

// round 6
// speedup vs baseline: 22.1133x; 1.7003x over previous
#include <cuda_runtime.h>
#include <cuda_fp16.h>
#include <math_constants.h>

// Problem constants
#define D_MODEL   2048
#define N_HEADS   16
#define N_KV      4
#define DH        128
#define B_        2
#define T_        2048
#define QKV_DIM   3072          // 2048 + 2*4*128
#define ROWS      (B_*T_)       // 4096

// Scratch (static device allocations only)
__device__ __half  g_qkvh[ROWS * QKV_DIM];      // 24 MB
__device__ __half  g_yh  [ROWS * D_MODEL];      // 16 MB
__device__ __half  g_xh  [ROWS * D_MODEL];      // 16 MB  (fp16 x)
__device__ __half  g_wqT [QKV_DIM * D_MODEL];   // 12 MB  (fp16 Wqkv^T  [N][K])
__device__ __half  g_woT [D_MODEL * D_MODEL];   //  8 MB  (fp16 Wo^T    [N][K])
__device__ float2  g_rtab[T_ * 64];             //  1 MB  (cos/sin table)

// ---------------------------------------------------------------------------
// helpers
// ---------------------------------------------------------------------------
__device__ __forceinline__ void mma16(float c[4], const unsigned a[4],
                                      unsigned b0, unsigned b1) {
    asm volatile(
        "mma.sync.aligned.m16n8k16.row.col.f32.f16.f16.f32 "
        "{%0,%1,%2,%3},{%4,%5,%6,%7},{%8,%9},{%0,%1,%2,%3};"
        : "+f"(c[0]), "+f"(c[1]), "+f"(c[2]), "+f"(c[3])
        : "r"(a[0]), "r"(a[1]), "r"(a[2]), "r"(a[3]), "r"(b0), "r"(b1));
}

#define LDM4(d, addr) \
    asm volatile("ldmatrix.sync.aligned.m8n8.x4.shared.b16 {%0,%1,%2,%3}, [%4];" \
        : "=r"((d)[0]), "=r"((d)[1]), "=r"((d)[2]), "=r"((d)[3]) : "r"(addr))
#define LDM4T(d, addr) \
    asm volatile("ldmatrix.sync.aligned.m8n8.x4.trans.shared.b16 {%0,%1,%2,%3}, [%4];" \
        : "=r"((d)[0]), "=r"((d)[1]), "=r"((d)[2]), "=r"((d)[3]) : "r"(addr))

#define CPA16(dst_u32, src_ptr) \
    asm volatile("cp.async.cg.shared.global [%0], [%1], 16;" :: "r"(dst_u32), "l"(src_ptr))
#define CPA_COMMIT() asm volatile("cp.async.commit_group;")
#define CPA_WAIT(n)  asm volatile("cp.async.wait_group %0;" :: "n"(n))

// ---------------------------------------------------------------------------
// pre-pass: fp32 -> fp16 conversion of x
// ---------------------------------------------------------------------------
__global__ __launch_bounds__(256) void conv_h_kernel(const float* __restrict__ in,
                                                     __half2* __restrict__ out, int n4) {
    int i = blockIdx.x * 256 + threadIdx.x;
    if (i >= n4) return;
    float4 v = ((const float4*)in)[i];
    out[2 * i]     = __floats2half2_rn(v.x, v.y);
    out[2 * i + 1] = __floats2half2_rn(v.z, v.w);
}

// ---------------------------------------------------------------------------
// pre-pass: transpose + convert weights: W[K][N] fp32 -> WT[N][K] fp16
// ---------------------------------------------------------------------------
__global__ __launch_bounds__(256) void transpose_h_kernel(const float* __restrict__ in,
                                                          __half* __restrict__ out,
                                                          int K, int N) {
    __shared__ float tile[32][33];
    const int tx = threadIdx.x, ty = threadIdx.y;
    const int n0 = blockIdx.x * 32, k0 = blockIdx.y * 32;
#pragma unroll
    for (int j = 0; j < 4; j++)
        tile[ty + 8 * j][tx] = in[(size_t)(k0 + ty + 8 * j) * N + n0 + tx];
    __syncthreads();
#pragma unroll
    for (int j = 0; j < 4; j++)
        out[(size_t)(n0 + ty + 8 * j) * K + k0 + tx] = __float2half(tile[tx][ty + 8 * j]);
}

// ---------------------------------------------------------------------------
// rope table: cos/sin for (t, i)
// ---------------------------------------------------------------------------
__global__ __launch_bounds__(256) void rope_table_kernel(const int* __restrict__ start_pos) {
    int id = blockIdx.x * 256 + threadIdx.x;    // < 2048*64
    int t = id >> 6, i = id & 63;
    float pos = (float)(start_pos[0] + t);
    float inv = exp2f(-(float)i * (13.287712379549449f / 64.0f));
    float ang = pos * inv;
    float s, c;
    sincosf(ang, &s, &c);
    g_rtab[id] = make_float2(c, s);
}

// ---------------------------------------------------------------------------
// RoPE on fp16 qkv (q,k regions only; v untouched). One block per row.
// Each rope pair = adjacent halves = one half2. 1280 half2 per row.
// ---------------------------------------------------------------------------
__global__ __launch_bounds__(256) void rope_h_kernel(__half2* __restrict__ qkv2) {
    const int row = blockIdx.x;
    const int t = row & (T_ - 1);
    const float2* tab = g_rtab + t * 64;
#pragma unroll
    for (int it = 0; it < 5; it++) {
        const int c2 = threadIdx.x + it * 256;       // 0..1279
        const int i = c2 & 63;                       // pair index within head
        float2 cs = tab[i];
        const size_t idx = (size_t)row * (QKV_DIM / 2) + c2;
        float2 v = __half22float2(qkv2[idx]);
        float e = v.x * cs.x - v.y * cs.y;
        float o = v.x * cs.y + v.y * cs.x;
        qkv2[idx] = __floats2half2_rn(e, o);
    }
}

// ---------------------------------------------------------------------------
// fp16 GEMM: C[M,N] = A[M,K] @ BT[N][K]^T; fp32 accum.
// 128x128 block, BK=32, 256 threads (8 warps, 64x32 warp tile),
// cp.async double-buffered, ldmatrix frag loads.
// smem halves: A tile [128][40] (80B rows), B tile [128][40]; 2 stages each.
// ---------------------------------------------------------------------------
#define GSTAGE 10240                    // bytes per tile stage
#define GEMM_SMEM (4 * GSTAGE)          // 40960 bytes

template <bool HALF_OUT>
__global__ __launch_bounds__(256) void gemm_h(const __half* __restrict__ A,
                                              const __half* __restrict__ Bt,
                                              void* __restrict__ Cv,
                                              int M, int N, int K) {
    extern __shared__ char smraw[];
    const unsigned sb = (unsigned)__cvta_generic_to_shared(smraw);

    const int tid = threadIdx.x;
    const int wid = tid >> 5, lane = tid & 31;
    const int g = lane >> 2, t = lane & 3;
    const int j = lane & 7, s1 = (lane >> 3) & 1, s2 = (lane >> 4) & 1;
    const int warp_m = (wid >> 2) * 64;
    const int warp_n = (wid & 3) * 32;
    const int bx = blockIdx.x, by = blockIdx.y;

    // ldmatrix lane-address bases (bytes)
    const unsigned a_lane = (unsigned)((warp_m + s1 * 8 + j) * 80 + s2 * 16);
    const unsigned b_lane = (unsigned)((warp_n + s2 * 8 + j) * 80 + s1 * 16) + 2 * GSTAGE;

    // cp.async mapping: 2 chunks each for A and B per thread
    const int ldrow = tid >> 2;          // 0..63 (2 passes of 64 rows)
    const int ldc = (tid & 3) * 16;      // byte column 0..48

    const int nst = K / 32;

    float acc[4][4][4];
#pragma unroll
    for (int i = 0; i < 4; i++)
#pragma unroll
        for (int jj = 0; jj < 4; jj++)
#pragma unroll
            for (int k = 0; k < 4; k++) acc[i][jj][k] = 0.f;

    {
#pragma unroll
        for (int p = 0; p < 2; p++) {
            const int r = ldrow + p * 64;
            CPA16(sb + r * 80 + ldc, A + (size_t)(by * 128 + r) * K + ldc / 2);
            CPA16(sb + 2 * GSTAGE + r * 80 + ldc, Bt + (size_t)(bx * 128 + r) * K + ldc / 2);
        }
        CPA_COMMIT();
    }

    for (int kt = 0; kt < nst; kt++) {
        CPA_WAIT(0);
        __syncthreads();

        if (kt + 1 < nst) {
            const unsigned stg = ((kt + 1) & 1) * GSTAGE;
            const int k0 = (kt + 1) * 32;
#pragma unroll
            for (int p = 0; p < 2; p++) {
                const int r = ldrow + p * 64;
                CPA16(sb + stg + r * 80 + ldc, A + (size_t)(by * 128 + r) * K + k0 + ldc / 2);
                CPA16(sb + 2 * GSTAGE + stg + r * 80 + ldc, Bt + (size_t)(bx * 128 + r) * K + k0 + ldc / 2);
            }
            CPA_COMMIT();
        }

        const unsigned stg = (kt & 1) * GSTAGE;
#pragma unroll
        for (int kk = 0; kk < 2; kk++) {
            unsigned af[4][4], bf[2][4];
#pragma unroll
            for (int mt = 0; mt < 4; mt++)
                LDM4(af[mt], sb + stg + a_lane + mt * 1280 + kk * 32);
#pragma unroll
            for (int np = 0; np < 2; np++)
                LDM4(bf[np], sb + stg + b_lane + np * 1280 + kk * 32);
#pragma unroll
            for (int mt = 0; mt < 4; mt++)
#pragma unroll
                for (int np = 0; np < 2; np++) {
                    mma16(acc[mt][np * 2],     af[mt], bf[np][0], bf[np][1]);
                    mma16(acc[mt][np * 2 + 1], af[mt], bf[np][2], bf[np][3]);
                }
        }
    }

#pragma unroll
    for (int mt = 0; mt < 4; mt++) {
#pragma unroll
        for (int nt = 0; nt < 4; nt++) {
            const int r0 = by * 128 + warp_m + mt * 16 + g;
            const int c0 = bx * 128 + warp_n + nt * 8 + 2 * t;
            if (HALF_OUT) {
                __half* C = (__half*)Cv;
                *(__half2*)&C[(size_t)r0 * N + c0]       = __floats2half2_rn(acc[mt][nt][0], acc[mt][nt][1]);
                *(__half2*)&C[(size_t)(r0 + 8) * N + c0] = __floats2half2_rn(acc[mt][nt][2], acc[mt][nt][3]);
            } else {
                float* C = (float*)Cv;
                *(float2*)&C[(size_t)r0 * N + c0]       = make_float2(acc[mt][nt][0], acc[mt][nt][1]);
                *(float2*)&C[(size_t)(r0 + 8) * N + c0] = make_float2(acc[mt][nt][2], acc[mt][nt][3]);
            }
        }
    }
}

// ---------------------------------------------------------------------------
// Flash attention (causal, GQA), fp16 mma + ldmatrix, cp.async dbuf.
// 256 threads / 8 warps; q-tile 128 (16 rows/warp); kv-tile 64.
// smem bytes: Qs[128][136h] @0 (34816) | Ks 2x[64][136h] @34816 (34816)
//           | Vs 2x[64][128h sw] @69632 (32768) | Ps[128][72h] @102400 (18432)
// ---------------------------------------------------------------------------
#define FQ_OFF 0u
#define FK_OFF 34816u
#define FV_OFF 69632u
#define FP_OFF 102400u
#define FLASH_SMEM 120832

__global__ __launch_bounds__(256) void flash_h(const __half* __restrict__ qkv,
                                               __half* __restrict__ y) {
    extern __shared__ char smraw[];
    const unsigned sb = (unsigned)__cvta_generic_to_shared(smraw);
    __half* Ps = (__half*)(smraw + FP_OFF);

    const int tid = threadIdx.x;
    const int wid = tid >> 5, lane = tid & 31;
    const int g = lane >> 2, t = lane & 3;
    const int j = lane & 7, s1 = (lane >> 3) & 1, s2 = (lane >> 4) & 1;
    const int qb = gridDim.x - 1 - blockIdx.x;   // long blocks first
    const int h = blockIdx.y, b = blockIdx.z;
    const int kvh = h >> 2;
    const int q0 = wid * 16;
    const float SC = 0.08838834764831845f * 1.4426950408889634f;  // scale*log2(e)

    // ldmatrix lane bases (bytes)
    const unsigned q_lane = FQ_OFF + (unsigned)((q0 + s1 * 8 + j) * 272 + s2 * 16);
    const unsigned k_lane = FK_OFF + (unsigned)((s2 * 8 + j) * 272 + s1 * 16);
    const unsigned vrow   = (unsigned)((s1 * 8 + j) * 256);
    const unsigned p_lane = FP_OFF + (unsigned)((q0 + s1 * 8 + j) * 144 + s2 * 16);

    // loaders
    const int lrow16 = tid >> 4;         // 0..15
    const int lc = tid & 15;             // chunk in row (16B units)

    // Q tile via cp.async (group 0): 128 rows x 16 chunks
#pragma unroll
    for (int it = 0; it < 8; it++) {
        const int row = it * 16 + lrow16;
        CPA16(sb + FQ_OFF + row * 272 + lc * 16,
              qkv + (size_t)(b * T_ + qb * 128 + row) * QKV_DIM + h * DH + lc * 8);
    }
    CPA_COMMIT();

    const int ntiles = 2 * qb + 2;

    // KV stage 0 (group 1): 64 rows x 16 chunks each
    {
#pragma unroll
        for (int it = 0; it < 4; it++) {
            const int row = it * 16 + lrow16;
            const __half* gp = qkv + (size_t)(b * T_ + row) * QKV_DIM + D_MODEL + kvh * DH + lc * 8;
            CPA16(sb + FK_OFF + row * 272 + lc * 16, gp);
            CPA16(sb + FV_OFF + row * 256 + ((lc ^ (row & 7)) << 4), gp + N_KV * DH);
        }
        CPA_COMMIT();
    }

    float m_lo = -1e30f, m_hi = -1e30f, l_lo = 0.f, l_hi = 0.f;
    float o[16][4];
#pragma unroll
    for (int i = 0; i < 16; i++)
#pragma unroll
        for (int jj = 0; jj < 4; jj++) o[i][jj] = 0.f;

    for (int kt = 0; kt < ntiles; kt++) {
        if (kt + 1 < ntiles) {
            const unsigned stg = ((kt + 1) & 1);
#pragma unroll
            for (int it = 0; it < 4; it++) {
                const int row = it * 16 + lrow16;
                const __half* gp = qkv + (size_t)(b * T_ + (kt + 1) * 64 + row) * QKV_DIM
                                   + D_MODEL + kvh * DH + lc * 8;
                CPA16(sb + FK_OFF + stg * 17408 + row * 272 + lc * 16, gp);
                CPA16(sb + FV_OFF + stg * 16384 + row * 256 + ((lc ^ (row & 7)) << 4), gp + N_KV * DH);
            }
            CPA_COMMIT();
            CPA_WAIT(1);
        } else {
            CPA_WAIT(0);
        }
        __syncthreads();

        const unsigned kstg = (kt & 1) * 17408;
        const unsigned vstg = FV_OFF + (kt & 1) * 16384;

        // S = Q K^T  (per warp: m16 x n64, k=128)
        float s[8][4];
#pragma unroll
        for (int nt = 0; nt < 8; nt++)
#pragma unroll
            for (int jj = 0; jj < 4; jj++) s[nt][jj] = 0.f;

#pragma unroll
        for (int kk = 0; kk < 8; kk++) {
            unsigned a[4];
            LDM4(a, sb + q_lane + kk * 32);
#pragma unroll
            for (int np = 0; np < 4; np++) {
                unsigned kb[4];
                LDM4(kb, sb + k_lane + kstg + np * 4352 + kk * 32);
                mma16(s[np * 2],     a, kb[0], kb[1]);
                mma16(s[np * 2 + 1], a, kb[2], kb[3]);
            }
        }

        // scale + causal mask + row max
        const int rlo = qb * 128 + q0 + g;
        const int rhi = rlo + 8;
        const int cb = kt * 64;
        float ml = -1e30f, mh = -1e30f;
#pragma unroll
        for (int nt = 0; nt < 8; nt++) {
            const int c0 = cb + nt * 8 + 2 * t, c1 = c0 + 1;
            float x0 = s[nt][0] * SC; if (c0 > rlo) x0 = -1e30f;
            float x1 = s[nt][1] * SC; if (c1 > rlo) x1 = -1e30f;
            float x2 = s[nt][2] * SC; if (c0 > rhi) x2 = -1e30f;
            float x3 = s[nt][3] * SC; if (c1 > rhi) x3 = -1e30f;
            s[nt][0] = x0; s[nt][1] = x1; s[nt][2] = x2; s[nt][3] = x3;
            ml = fmaxf(ml, fmaxf(x0, x1));
            mh = fmaxf(mh, fmaxf(x2, x3));
        }
        ml = fmaxf(ml, __shfl_xor_sync(0xffffffffu, ml, 1));
        ml = fmaxf(ml, __shfl_xor_sync(0xffffffffu, ml, 2));
        mh = fmaxf(mh, __shfl_xor_sync(0xffffffffu, mh, 1));
        mh = fmaxf(mh, __shfl_xor_sync(0xffffffffu, mh, 2));

        const float mnl = fmaxf(m_lo, ml);
        const float mnh = fmaxf(m_hi, mh);
        const float al = exp2f(m_lo - mnl);
        const float ah = exp2f(m_hi - mnh);

        float ll = 0.f, lh = 0.f;
#pragma unroll
        for (int nt = 0; nt < 8; nt++) {
            float p0 = exp2f(s[nt][0] - mnl);
            float p1 = exp2f(s[nt][1] - mnl);
            float p2 = exp2f(s[nt][2] - mnh);
            float p3 = exp2f(s[nt][3] - mnh);
            ll += p0 + p1;
            lh += p2 + p3;
            *(__half2*)&Ps[(q0 + g) * 72 + nt * 8 + 2 * t]     = __floats2half2_rn(p0, p1);
            *(__half2*)&Ps[(q0 + 8 + g) * 72 + nt * 8 + 2 * t] = __floats2half2_rn(p2, p3);
        }
        ll += __shfl_xor_sync(0xffffffffu, ll, 1);
        ll += __shfl_xor_sync(0xffffffffu, ll, 2);
        lh += __shfl_xor_sync(0xffffffffu, lh, 1);
        lh += __shfl_xor_sync(0xffffffffu, lh, 2);

        l_lo = l_lo * al + ll;
        l_hi = l_hi * ah + lh;
        m_lo = mnl;
        m_hi = mnh;

#pragma unroll
        for (int nt = 0; nt < 16; nt++) {
            o[nt][0] *= al; o[nt][1] *= al;
            o[nt][2] *= ah; o[nt][3] *= ah;
        }
        __syncwarp();   // Ps rows are warp-private

        // O += P @ V  (per warp: m16 x n128, k=64); V frags via ldmatrix.trans
#pragma unroll
        for (int kk = 0; kk < 4; kk++) {
            unsigned a[4];
            LDM4(a, sb + p_lane + kk * 32);
#pragma unroll
            for (int np = 0; np < 8; np++) {
                unsigned vb[4];
                const unsigned chunk = (unsigned)(((np << 1) | s2) ^ j);
                LDM4T(vb, sb + vstg + kk * 4096 + vrow + (chunk << 4));
                mma16(o[np * 2],     a, vb[0], vb[1]);
                mma16(o[np * 2 + 1], a, vb[2], vb[3]);
            }
        }
        __syncthreads();   // compute done before next iter overwrites the other stage
    }

    // epilogue: normalize, write y (fp16)
    const float il = 1.f / l_lo;
    const float ih = 1.f / l_hi;
    const size_t rl = (size_t)(b * T_ + qb * 128 + q0 + g);
#pragma unroll
    for (int nt = 0; nt < 16; nt++) {
        const int c = h * DH + nt * 8 + 2 * t;
        *(__half2*)&y[rl * D_MODEL + c]       = __floats2half2_rn(o[nt][0] * il, o[nt][1] * il);
        *(__half2*)&y[(rl + 8) * D_MODEL + c] = __floats2half2_rn(o[nt][2] * ih, o[nt][3] * ih);
    }
}

// ---------------------------------------------------------------------------
// Launch
// ---------------------------------------------------------------------------
extern "C" void kernel_launch(void* const* d_in, const int* in_sizes, int n_in,
                              void* d_out, int out_size) {
    const float* x        = (const float*)d_in[0];   // (2, 2048, 2048)
    const float* Wqkv     = (const float*)d_in[1];   // (2048, 3072)
    const float* Wo       = (const float*)d_in[2];   // (2048, 2048)
    const int*   startpos = (const int*)d_in[3];     // scalar
    float* out = (float*)d_out;                      // (2, 2048, 2048)

    __half *qkvh, *yh, *xh, *wqT, *woT;
    cudaGetSymbolAddress((void**)&qkvh, g_qkvh);
    cudaGetSymbolAddress((void**)&yh, g_yh);
    cudaGetSymbolAddress((void**)&xh, g_xh);
    cudaGetSymbolAddress((void**)&wqT, g_wqT);
    cudaGetSymbolAddress((void**)&woT, g_woT);

    cudaFuncSetAttribute(gemm_h<true>,  cudaFuncAttributeMaxDynamicSharedMemorySize, GEMM_SMEM);
    cudaFuncSetAttribute(gemm_h<false>, cudaFuncAttributeMaxDynamicSharedMemorySize, GEMM_SMEM);
    cudaFuncSetAttribute(flash_h, cudaFuncAttributeMaxDynamicSharedMemorySize, FLASH_SMEM);

    // 0) pre-pass: fp16 conversions + weight transposes + rope table
    conv_h_kernel<<<(ROWS * D_MODEL / 4 + 255) / 256, 256>>>(x, (__half2*)xh, ROWS * D_MODEL / 4);
    transpose_h_kernel<<<dim3(QKV_DIM / 32, D_MODEL / 32), dim3(32, 8)>>>(Wqkv, wqT, D_MODEL, QKV_DIM);
    transpose_h_kernel<<<dim3(D_MODEL / 32, D_MODEL / 32), dim3(32, 8)>>>(Wo, woT, D_MODEL, D_MODEL);
    rope_table_kernel<<<T_ * 64 / 256, 256>>>(startpos);

    // 1) qkv = x @ Wqkv   (fp16 out)
    dim3 g1(QKV_DIM / 128, ROWS / 128);
    gemm_h<true><<<g1, 256, GEMM_SMEM>>>(xh, wqT, qkvh, ROWS, QKV_DIM, D_MODEL);

    // 2) RoPE in-place on q,k (fp16)
    rope_h_kernel<<<ROWS, 256>>>((__half2*)qkvh);

    // 3) flash attention -> yh (fp16)
    dim3 g3(T_ / 128, N_HEADS, B_);
    flash_h<<<g3, 256, FLASH_SMEM>>>(qkvh, yh);

    // 4) out = y @ Wo  (fp32 out)
    dim3 g4(D_MODEL / 128, ROWS / 128);
    gemm_h<false><<<g4, 256, GEMM_SMEM>>>(yh, woT, out, ROWS, D_MODEL, D_MODEL);
}

// round 10
// speedup vs baseline: 24.2063x; 1.0947x over previous
#include <cuda_runtime.h>
#include <cuda_fp16.h>
#include <math_constants.h>
#include <cstdint>

// Problem constants
#define D_MODEL   2048
#define N_HEADS   16
#define N_KV      4
#define DH        128
#define B_        2
#define T_        2048
#define QKV_DIM   3072          // 2048 + 2*4*128
#define ROWS      (B_*T_)       // 4096

// Scratch (static device allocations only)
__device__ __half  g_qkvh[ROWS * QKV_DIM];      // 24 MB
__device__ __half  g_yh  [ROWS * D_MODEL];      // 16 MB
__device__ __half  g_xh  [ROWS * D_MODEL];      // 16 MB  (fp16 x)
__device__ __half  g_wqT [QKV_DIM * D_MODEL];   // 12 MB  (fp16 Wqkv^T  [N][K])
__device__ __half  g_woT [D_MODEL * D_MODEL];   //  8 MB  (fp16 Wo^T    [N][K])
__device__ float2  g_rtab[T_ * 64];             //  1 MB  (cos/sin table)

// ---------------------------------------------------------------------------
// helpers
// ---------------------------------------------------------------------------
__device__ __forceinline__ void mma16(float c[4], const unsigned a[4],
                                      unsigned b0, unsigned b1) {
    asm volatile(
        "mma.sync.aligned.m16n8k16.row.col.f32.f16.f16.f32 "
        "{%0,%1,%2,%3},{%4,%5,%6,%7},{%8,%9},{%0,%1,%2,%3};"
        : "+f"(c[0]), "+f"(c[1]), "+f"(c[2]), "+f"(c[3])
        : "r"(a[0]), "r"(a[1]), "r"(a[2]), "r"(a[3]), "r"(b0), "r"(b1));
}

#define LDM4(d, addr) \
    asm volatile("ldmatrix.sync.aligned.m8n8.x4.shared.b16 {%0,%1,%2,%3}, [%4];" \
        : "=r"((d)[0]), "=r"((d)[1]), "=r"((d)[2]), "=r"((d)[3]) : "r"(addr))
#define LDM4T(d, addr) \
    asm volatile("ldmatrix.sync.aligned.m8n8.x4.trans.shared.b16 {%0,%1,%2,%3}, [%4];" \
        : "=r"((d)[0]), "=r"((d)[1]), "=r"((d)[2]), "=r"((d)[3]) : "r"(addr))

#define CPA16(dst_u32, src_ptr) \
    asm volatile("cp.async.cg.shared.global [%0], [%1], 16;" :: "r"(dst_u32), "l"(src_ptr))
#define CPA_COMMIT() asm volatile("cp.async.commit_group;")
#define CPA_WAIT(n)  asm volatile("cp.async.wait_group %0;" :: "n"(n))

__device__ __forceinline__ unsigned h2u(__half2 h) { return *(unsigned*)&h; }

// ---------------------------------------------------------------------------
// pre-pass: fp32 -> fp16 conversion of x
// ---------------------------------------------------------------------------
__global__ __launch_bounds__(256) void conv_h_kernel(const float* __restrict__ in,
                                                     __half2* __restrict__ out, int n4) {
    int i = blockIdx.x * 256 + threadIdx.x;
    if (i >= n4) return;
    float4 v = ((const float4*)in)[i];
    out[2 * i]     = __floats2half2_rn(v.x, v.y);
    out[2 * i + 1] = __floats2half2_rn(v.z, v.w);
}

// ---------------------------------------------------------------------------
// pre-pass: transpose + convert weights: W[K][N] fp32 -> WT[N][K] fp16
// ---------------------------------------------------------------------------
__global__ __launch_bounds__(256) void transpose_h_kernel(const float* __restrict__ in,
                                                          __half* __restrict__ out,
                                                          int K, int N) {
    __shared__ float tile[32][33];
    const int tx = threadIdx.x, ty = threadIdx.y;
    const int n0 = blockIdx.x * 32, k0 = blockIdx.y * 32;
#pragma unroll
    for (int j = 0; j < 4; j++)
        tile[ty + 8 * j][tx] = in[(size_t)(k0 + ty + 8 * j) * N + n0 + tx];
    __syncthreads();
#pragma unroll
    for (int j = 0; j < 4; j++)
        out[(size_t)(n0 + ty + 8 * j) * K + k0 + tx] = __float2half(tile[tx][ty + 8 * j]);
}

// ---------------------------------------------------------------------------
// rope table: cos/sin for (t, i)
// ---------------------------------------------------------------------------
__global__ __launch_bounds__(256) void rope_table_kernel(const int* __restrict__ start_pos) {
    int id = blockIdx.x * 256 + threadIdx.x;    // < 2048*64
    int t = id >> 6, i = id & 63;
    float pos = (float)(start_pos[0] + t);
    float inv = exp2f(-(float)i * (13.287712379549449f / 64.0f));
    float ang = pos * inv;
    float s, c;
    sincosf(ang, &s, &c);
    g_rtab[id] = make_float2(c, s);
}

// ---------------------------------------------------------------------------
// fp16 GEMM: C[M,N] = A[M,K] @ BT[N][K]^T; fp32 accum.
// 128x128 block, BK=32, 256 threads (8 warps, 64x32 warp tile),
// cp.async double-buffered, ldmatrix frag loads.
// ROPE: apply rotary embedding in the epilogue for columns < 2560 (q,k regions).
// ---------------------------------------------------------------------------
#define GSTAGE 10240                    // bytes per tile stage
#define GEMM_SMEM (4 * GSTAGE)          // 40960 bytes

template <bool HALF_OUT, bool ROPE>
__global__ __launch_bounds__(256) void gemm_h(const __half* __restrict__ A,
                                              const __half* __restrict__ Bt,
                                              void* __restrict__ Cv,
                                              int M, int N, int K) {
    extern __shared__ char smraw[];
    const unsigned sb = (unsigned)__cvta_generic_to_shared(smraw);

    const int tid = threadIdx.x;
    const int wid = tid >> 5, lane = tid & 31;
    const int g = lane >> 2, t = lane & 3;
    const int j = lane & 7, s1 = (lane >> 3) & 1, s2 = (lane >> 4) & 1;
    const int warp_m = (wid >> 2) * 64;
    const int warp_n = (wid & 3) * 32;
    const int bx = blockIdx.x, by = blockIdx.y;

    const unsigned a_lane = (unsigned)((warp_m + s1 * 8 + j) * 80 + s2 * 16);
    const unsigned b_lane = (unsigned)((warp_n + s2 * 8 + j) * 80 + s1 * 16) + 2 * GSTAGE;

    const int ldrow = tid >> 2;          // 0..63 (2 passes of 64 rows)
    const int ldc = (tid & 3) * 16;      // byte column 0..48

    const int nst = K / 32;

    float acc[4][4][4];
#pragma unroll
    for (int i = 0; i < 4; i++)
#pragma unroll
        for (int jj = 0; jj < 4; jj++)
#pragma unroll
            for (int k = 0; k < 4; k++) acc[i][jj][k] = 0.f;

    {
#pragma unroll
        for (int p = 0; p < 2; p++) {
            const int r = ldrow + p * 64;
            CPA16(sb + r * 80 + ldc, A + (size_t)(by * 128 + r) * K + ldc / 2);
            CPA16(sb + 2 * GSTAGE + r * 80 + ldc, Bt + (size_t)(bx * 128 + r) * K + ldc / 2);
        }
        CPA_COMMIT();
    }

    for (int kt = 0; kt < nst; kt++) {
        CPA_WAIT(0);
        __syncthreads();

        if (kt + 1 < nst) {
            const unsigned stg = ((kt + 1) & 1) * GSTAGE;
            const int k0 = (kt + 1) * 32;
#pragma unroll
            for (int p = 0; p < 2; p++) {
                const int r = ldrow + p * 64;
                CPA16(sb + stg + r * 80 + ldc, A + (size_t)(by * 128 + r) * K + k0 + ldc / 2);
                CPA16(sb + 2 * GSTAGE + stg + r * 80 + ldc, Bt + (size_t)(bx * 128 + r) * K + k0 + ldc / 2);
            }
            CPA_COMMIT();
        }

        const unsigned stg = (kt & 1) * GSTAGE;
#pragma unroll
        for (int kk = 0; kk < 2; kk++) {
            unsigned af[4][4], bf[2][4];
#pragma unroll
            for (int mt = 0; mt < 4; mt++)
                LDM4(af[mt], sb + stg + a_lane + mt * 1280 + kk * 32);
#pragma unroll
            for (int np = 0; np < 2; np++)
                LDM4(bf[np], sb + stg + b_lane + np * 1280 + kk * 32);
#pragma unroll
            for (int mt = 0; mt < 4; mt++)
#pragma unroll
                for (int np = 0; np < 2; np++) {
                    mma16(acc[mt][np * 2],     af[mt], bf[np][0], bf[np][1]);
                    mma16(acc[mt][np * 2 + 1], af[mt], bf[np][2], bf[np][3]);
                }
        }
    }

#pragma unroll
    for (int mt = 0; mt < 4; mt++) {
#pragma unroll
        for (int nt = 0; nt < 4; nt++) {
            const int r0 = by * 128 + warp_m + mt * 16 + g;
            const int c0 = bx * 128 + warp_n + nt * 8 + 2 * t;
            float v0 = acc[mt][nt][0], v1 = acc[mt][nt][1];
            float v2 = acc[mt][nt][2], v3 = acc[mt][nt][3];
            if (ROPE && c0 < 2560) {
                const int i = (c0 & 127) >> 1;
                float2 csA = g_rtab[(r0 & (T_ - 1)) * 64 + i];
                float2 csB = g_rtab[((r0 + 8) & (T_ - 1)) * 64 + i];
                float e0 = v0 * csA.x - v1 * csA.y;
                float o0 = v0 * csA.y + v1 * csA.x;
                float e1 = v2 * csB.x - v3 * csB.y;
                float o1 = v2 * csB.y + v3 * csB.x;
                v0 = e0; v1 = o0; v2 = e1; v3 = o1;
            }
            if (HALF_OUT) {
                __half* C = (__half*)Cv;
                *(__half2*)&C[(size_t)r0 * N + c0]       = __floats2half2_rn(v0, v1);
                *(__half2*)&C[(size_t)(r0 + 8) * N + c0] = __floats2half2_rn(v2, v3);
            } else {
                float* C = (float*)Cv;
                *(float2*)&C[(size_t)r0 * N + c0]       = make_float2(v0, v1);
                *(float2*)&C[(size_t)(r0 + 8) * N + c0] = make_float2(v2, v3);
            }
        }
    }
}

// ---------------------------------------------------------------------------
// Flash attention (causal, GQA), fp16 mma + ldmatrix, cp.async dbuf.
// 128 threads / 4 warps; q-tile 64 (16 rows/warp); kv-tile 64.
// P kept in registers (S-accum frags reused directly as PV A-frags).
// smem bytes: Qs[64][272B] @0 (17408) | Ks 2x[64][272B] @17408 (34816)
//           | Vs 2x[64][256B sw] @52224 (32768)  => 84992 total (2 CTAs/SM)
// ---------------------------------------------------------------------------
#define FQ_OFF 0u
#define FK_OFF 17408u
#define FV_OFF 52224u
#define FLASH_SMEM 84992

__global__ __launch_bounds__(128, 2) void flash_h(const __half* __restrict__ qkv,
                                                  __half* __restrict__ y) {
    extern __shared__ char smraw[];
    const unsigned sb = (unsigned)__cvta_generic_to_shared(smraw);

    const int tid = threadIdx.x;
    const int wid = tid >> 5, lane = tid & 31;
    const int g = lane >> 2, t = lane & 3;
    const int j = lane & 7, s1 = (lane >> 3) & 1, s2 = (lane >> 4) & 1;
    const int qb = gridDim.x - 1 - blockIdx.x;   // long blocks first
    const int h = blockIdx.y, b = blockIdx.z;
    const int kvh = h >> 2;
    const int q0 = wid * 16;
    const float SC = 0.08838834764831845f * 1.4426950408889634f;  // scale*log2(e)

    // ldmatrix lane bases (bytes)
    const unsigned q_lane = FQ_OFF + (unsigned)((q0 + s1 * 8 + j) * 272 + s2 * 16);
    const unsigned k_lane = FK_OFF + (unsigned)((s2 * 8 + j) * 272 + s1 * 16);
    const unsigned vrow   = (unsigned)((s1 * 8 + j) * 256);

    // loaders: 128 threads, 8 iters of 8 rows x 16 chunks
    const int lrow8 = tid >> 4;          // 0..7
    const int lc = tid & 15;             // 16B chunk within row

    // Q tile (group 0): 64 rows
#pragma unroll
    for (int it = 0; it < 4; it++) {
        const int row = it * 16 + (tid >> 4) + ((tid & 8) ? 0 : 0); // rows via lrow8 pattern below
    }
    // (use simple 8-iter loop)
#pragma unroll
    for (int it = 0; it < 8; it++) {
        const int row = it * 8 + lrow8;
        CPA16(sb + FQ_OFF + row * 272 + lc * 16,
              qkv + (size_t)(b * T_ + qb * 64 + row) * QKV_DIM + h * DH + lc * 8);
    }
    CPA_COMMIT();

    const int ntiles = qb + 1;

    // KV stage 0 (group 1)
    {
#pragma unroll
        for (int it = 0; it < 8; it++) {
            const int row = it * 8 + lrow8;
            const __half* gp = qkv + (size_t)(b * T_ + row) * QKV_DIM + D_MODEL + kvh * DH + lc * 8;
            CPA16(sb + FK_OFF + row * 272 + lc * 16, gp);
            CPA16(sb + FV_OFF + row * 256 + ((lc ^ (row & 7)) << 4), gp + N_KV * DH);
        }
        CPA_COMMIT();
    }

    float m_lo = -1e30f, m_hi = -1e30f, l_lo = 0.f, l_hi = 0.f;
    float o[16][4];
#pragma unroll
    for (int i = 0; i < 16; i++)
#pragma unroll
        for (int jj = 0; jj < 4; jj++) o[i][jj] = 0.f;

    for (int kt = 0; kt < ntiles; kt++) {
        if (kt + 1 < ntiles) {
            const unsigned stg = ((kt + 1) & 1);
#pragma unroll
            for (int it = 0; it < 8; it++) {
                const int row = it * 8 + lrow8;
                const __half* gp = qkv + (size_t)(b * T_ + (kt + 1) * 64 + row) * QKV_DIM
                                   + D_MODEL + kvh * DH + lc * 8;
                CPA16(sb + FK_OFF + stg * 17408 + row * 272 + lc * 16, gp);
                CPA16(sb + FV_OFF + stg * 16384 + row * 256 + ((lc ^ (row & 7)) << 4), gp + N_KV * DH);
            }
            CPA_COMMIT();
            CPA_WAIT(1);
        } else {
            CPA_WAIT(0);
        }
        __syncthreads();

        const unsigned kstg = (kt & 1) * 17408;
        const unsigned vstg = FV_OFF + (kt & 1) * 16384;

        // S = Q K^T  (per warp: m16 x n64, k=128)
        float s[8][4];
#pragma unroll
        for (int nt = 0; nt < 8; nt++)
#pragma unroll
            for (int jj = 0; jj < 4; jj++) s[nt][jj] = 0.f;

#pragma unroll
        for (int kk = 0; kk < 8; kk++) {
            unsigned a[4];
            LDM4(a, sb + q_lane + kk * 32);
#pragma unroll
            for (int np = 0; np < 4; np++) {
                unsigned kb[4];
                LDM4(kb, sb + k_lane + kstg + np * 4352 + kk * 32);
                mma16(s[np * 2],     a, kb[0], kb[1]);
                mma16(s[np * 2 + 1], a, kb[2], kb[3]);
            }
        }

        // scale + causal mask + row max (rows g and g+8)
        const int rlo = qb * 64 + q0 + g;
        const int rhi = rlo + 8;
        const int cb = kt * 64;
        float ml = -1e30f, mh = -1e30f;
#pragma unroll
        for (int nt = 0; nt < 8; nt++) {
            const int c0 = cb + nt * 8 + 2 * t, c1 = c0 + 1;
            float x0 = s[nt][0] * SC; if (c0 > rlo) x0 = -1e30f;
            float x1 = s[nt][1] * SC; if (c1 > rlo) x1 = -1e30f;
            float x2 = s[nt][2] * SC; if (c0 > rhi) x2 = -1e30f;
            float x3 = s[nt][3] * SC; if (c1 > rhi) x3 = -1e30f;
            s[nt][0] = x0; s[nt][1] = x1; s[nt][2] = x2; s[nt][3] = x3;
            ml = fmaxf(ml, fmaxf(x0, x1));
            mh = fmaxf(mh, fmaxf(x2, x3));
        }
        ml = fmaxf(ml, __shfl_xor_sync(0xffffffffu, ml, 1));
        ml = fmaxf(ml, __shfl_xor_sync(0xffffffffu, ml, 2));
        mh = fmaxf(mh, __shfl_xor_sync(0xffffffffu, mh, 1));
        mh = fmaxf(mh, __shfl_xor_sync(0xffffffffu, mh, 2));

        const float mnl = fmaxf(m_lo, ml);
        const float mnh = fmaxf(m_hi, mh);
        const float al = exp2f(m_lo - mnl);
        const float ah = exp2f(m_hi - mnh);

        // exp2 -> P stays in registers (fp32 in s[][])
        float ll = 0.f, lh = 0.f;
#pragma unroll
        for (int nt = 0; nt < 8; nt++) {
            s[nt][0] = exp2f(s[nt][0] - mnl);
            s[nt][1] = exp2f(s[nt][1] - mnl);
            s[nt][2] = exp2f(s[nt][2] - mnh);
            s[nt][3] = exp2f(s[nt][3] - mnh);
            ll += s[nt][0] + s[nt][1];
            lh += s[nt][2] + s[nt][3];
        }
        ll += __shfl_xor_sync(0xffffffffu, ll, 1);
        ll += __shfl_xor_sync(0xffffffffu, ll, 2);
        lh += __shfl_xor_sync(0xffffffffu, lh, 1);
        lh += __shfl_xor_sync(0xffffffffu, lh, 2);

        l_lo = l_lo * al + ll;
        l_hi = l_hi * ah + lh;
        m_lo = mnl;
        m_hi = mnh;

#pragma unroll
        for (int nt = 0; nt < 16; nt++) {
            o[nt][0] *= al; o[nt][1] *= al;
            o[nt][2] *= ah; o[nt][3] *= ah;
        }

        // O += P @ V  (per warp: m16 x n128, k=64)
        // A-frags for k-block kk built directly from S accumulators:
        //   a0=(g,  2t..2t+1 of tile 2kk)   = s[2kk][0..1]
        //   a1=(g+8, same)                  = s[2kk][2..3]
        //   a2=(g,  of tile 2kk+1)          = s[2kk+1][0..1]
        //   a3=(g+8, of tile 2kk+1)         = s[2kk+1][2..3]
#pragma unroll
        for (int kk = 0; kk < 4; kk++) {
            unsigned a[4];
            a[0] = h2u(__floats2half2_rn(s[2 * kk][0],     s[2 * kk][1]));
            a[1] = h2u(__floats2half2_rn(s[2 * kk][2],     s[2 * kk][3]));
            a[2] = h2u(__floats2half2_rn(s[2 * kk + 1][0], s[2 * kk + 1][1]));
            a[3] = h2u(__floats2half2_rn(s[2 * kk + 1][2], s[2 * kk + 1][3]));
#pragma unroll
            for (int np = 0; np < 8; np++) {
                unsigned vb[4];
                const unsigned chunk = (unsigned)(((np << 1) | s2) ^ j);
                LDM4T(vb, sb + vstg + kk * 4096 + vrow + (chunk << 4));
                mma16(o[np * 2],     a, vb[0], vb[1]);
                mma16(o[np * 2 + 1], a, vb[2], vb[3]);
            }
        }
        __syncthreads();   // all warps done with this stage before it is reloaded
    }

    // epilogue: normalize, write y (fp16)
    const float il = 1.f / l_lo;
    const float ih = 1.f / l_hi;
    const size_t rl = (size_t)(b * T_ + qb * 64 + q0 + g);
#pragma unroll
    for (int nt = 0; nt < 16; nt++) {
        const int c = h * DH + nt * 8 + 2 * t;
        *(__half2*)&y[rl * D_MODEL + c]       = __floats2half2_rn(o[nt][0] * il, o[nt][1] * il);
        *(__half2*)&y[(rl + 8) * D_MODEL + c] = __floats2half2_rn(o[nt][2] * ih, o[nt][3] * ih);
    }
}

// ---------------------------------------------------------------------------
// Launch
// ---------------------------------------------------------------------------
extern "C" void kernel_launch(void* const* d_in, const int* in_sizes, int n_in,
                              void* d_out, int out_size) {
    const float* x        = (const float*)d_in[0];   // (2, 2048, 2048)
    const float* Wqkv     = (const float*)d_in[1];   // (2048, 3072)
    const float* Wo       = (const float*)d_in[2];   // (2048, 2048)
    const int*   startpos = (const int*)d_in[3];     // scalar
    float* out = (float*)d_out;                      // (2, 2048, 2048)

    __half *qkvh, *yh, *xh, *wqT, *woT;
    cudaGetSymbolAddress((void**)&qkvh, g_qkvh);
    cudaGetSymbolAddress((void**)&yh, g_yh);
    cudaGetSymbolAddress((void**)&xh, g_xh);
    cudaGetSymbolAddress((void**)&wqT, g_wqT);
    cudaGetSymbolAddress((void**)&woT, g_woT);

    cudaFuncSetAttribute((void*)gemm_h<true, true>,   cudaFuncAttributeMaxDynamicSharedMemorySize, GEMM_SMEM);
    cudaFuncSetAttribute((void*)gemm_h<false, false>, cudaFuncAttributeMaxDynamicSharedMemorySize, GEMM_SMEM);
    cudaFuncSetAttribute((void*)flash_h, cudaFuncAttributeMaxDynamicSharedMemorySize, FLASH_SMEM);

    // 0) pre-pass: fp16 conversions + weight transposes + rope table
    conv_h_kernel<<<(ROWS * D_MODEL / 4 + 255) / 256, 256>>>(x, (__half2*)xh, ROWS * D_MODEL / 4);
    transpose_h_kernel<<<dim3(QKV_DIM / 32, D_MODEL / 32), dim3(32, 8)>>>(Wqkv, wqT, D_MODEL, QKV_DIM);
    transpose_h_kernel<<<dim3(D_MODEL / 32, D_MODEL / 32), dim3(32, 8)>>>(Wo, woT, D_MODEL, D_MODEL);
    rope_table_kernel<<<T_ * 64 / 256, 256>>>(startpos);

    // 1) qkv = x @ Wqkv with fused RoPE (fp16 out)
    dim3 g1(QKV_DIM / 128, ROWS / 128);
    gemm_h<true, true><<<g1, 256, GEMM_SMEM>>>(xh, wqT, qkvh, ROWS, QKV_DIM, D_MODEL);

    // 2) flash attention -> yh (fp16)
    dim3 g3(T_ / 64, N_HEADS, B_);
    flash_h<<<g3, 128, FLASH_SMEM>>>(qkvh, yh);

    // 3) out = y @ Wo  (fp32 out)
    dim3 g4(D_MODEL / 128, ROWS / 128);
    gemm_h<false, false><<<g4, 256, GEMM_SMEM>>>(yh, woT, out, ROWS, D_MODEL, D_MODEL);
}

// round 11
// speedup vs baseline: 28.4919x; 1.1770x over previous
#include <cuda_runtime.h>
#include <cuda_fp16.h>
#include <math_constants.h>
#include <cstdint>

// Problem constants
#define D_MODEL   2048
#define N_HEADS   16
#define N_KV      4
#define DH        128
#define B_        2
#define T_        2048
#define QKV_DIM   3072          // 2048 + 2*4*128
#define ROWS      (B_*T_)       // 4096

// Scratch (static device allocations only)
__device__ __half  g_qkvh[ROWS * QKV_DIM];      // 24 MB
__device__ __half  g_yh  [ROWS * D_MODEL];      // 16 MB
__device__ __half  g_xh  [ROWS * D_MODEL];      // 16 MB  (fp16 x)
__device__ __half  g_wqT [QKV_DIM * D_MODEL];   // 12 MB  (fp16 Wqkv^T  [N][K])
__device__ __half  g_woT [D_MODEL * D_MODEL];   //  8 MB  (fp16 Wo^T    [N][K])
__device__ float2  g_rtab[T_ * 64];             //  1 MB  (cos/sin table)

// ---------------------------------------------------------------------------
// helpers
// ---------------------------------------------------------------------------
__device__ __forceinline__ void mma16(float c[4], const unsigned a[4],
                                      unsigned b0, unsigned b1) {
    asm volatile(
        "mma.sync.aligned.m16n8k16.row.col.f32.f16.f16.f32 "
        "{%0,%1,%2,%3},{%4,%5,%6,%7},{%8,%9},{%0,%1,%2,%3};"
        : "+f"(c[0]), "+f"(c[1]), "+f"(c[2]), "+f"(c[3])
        : "r"(a[0]), "r"(a[1]), "r"(a[2]), "r"(a[3]), "r"(b0), "r"(b1));
}

#define LDM4(d, addr) \
    asm volatile("ldmatrix.sync.aligned.m8n8.x4.shared.b16 {%0,%1,%2,%3}, [%4];" \
        : "=r"((d)[0]), "=r"((d)[1]), "=r"((d)[2]), "=r"((d)[3]) : "r"(addr))
#define LDM4T(d, addr) \
    asm volatile("ldmatrix.sync.aligned.m8n8.x4.trans.shared.b16 {%0,%1,%2,%3}, [%4];" \
        : "=r"((d)[0]), "=r"((d)[1]), "=r"((d)[2]), "=r"((d)[3]) : "r"(addr))

#define CPA16(dst_u32, src_ptr) \
    asm volatile("cp.async.cg.shared.global [%0], [%1], 16;" :: "r"(dst_u32), "l"(src_ptr))
#define CPA_COMMIT() asm volatile("cp.async.commit_group;")
#define CPA_WAIT(n)  asm volatile("cp.async.wait_group %0;" :: "n"(n))

__device__ __forceinline__ unsigned h2u(__half2 h) { return *(unsigned*)&h; }
__device__ __forceinline__ float ex2f(float x) {
    float r;
    asm("ex2.approx.ftz.f32 %0, %1;" : "=f"(r) : "f"(x));
    return r;
}

// ---------------------------------------------------------------------------
// pre-pass: fp32 -> fp16 conversion of x
// ---------------------------------------------------------------------------
__global__ __launch_bounds__(256) void conv_h_kernel(const float* __restrict__ in,
                                                     __half2* __restrict__ out, int n4) {
    int i = blockIdx.x * 256 + threadIdx.x;
    if (i >= n4) return;
    float4 v = ((const float4*)in)[i];
    out[2 * i]     = __floats2half2_rn(v.x, v.y);
    out[2 * i + 1] = __floats2half2_rn(v.z, v.w);
}

// ---------------------------------------------------------------------------
// pre-pass: transpose + convert weights: W[K][N] fp32 -> WT[N][K] fp16
// ---------------------------------------------------------------------------
__global__ __launch_bounds__(256) void transpose_h_kernel(const float* __restrict__ in,
                                                          __half* __restrict__ out,
                                                          int K, int N) {
    __shared__ float tile[32][33];
    const int tx = threadIdx.x, ty = threadIdx.y;
    const int n0 = blockIdx.x * 32, k0 = blockIdx.y * 32;
#pragma unroll
    for (int j = 0; j < 4; j++)
        tile[ty + 8 * j][tx] = in[(size_t)(k0 + ty + 8 * j) * N + n0 + tx];
    __syncthreads();
#pragma unroll
    for (int j = 0; j < 4; j++)
        out[(size_t)(n0 + ty + 8 * j) * K + k0 + tx] = __float2half(tile[tx][ty + 8 * j]);
}

// ---------------------------------------------------------------------------
// rope table: cos/sin for (t, i)
// ---------------------------------------------------------------------------
__global__ __launch_bounds__(256) void rope_table_kernel(const int* __restrict__ start_pos) {
    int id = blockIdx.x * 256 + threadIdx.x;    // < 2048*64
    int t = id >> 6, i = id & 63;
    float pos = (float)(start_pos[0] + t);
    float inv = exp2f(-(float)i * (13.287712379549449f / 64.0f));
    float ang = pos * inv;
    float s, c;
    sincosf(ang, &s, &c);
    g_rtab[id] = make_float2(c, s);
}

// ---------------------------------------------------------------------------
// fp16 GEMM: C[M,N] = A[M,K] @ BT[N][K]^T; fp32 accum.
// 128x128 CTA tile, 128 threads (4 warps, 64x64 warp tile), BK=64,
// 128B swizzled smem rows, cp.async double-buffered, ldmatrix frag loads.
// ROPE: rotary embedding fused into epilogue for columns < 2560 (q,k regions).
// ---------------------------------------------------------------------------
#define G2STAGE 32768                    // bytes per stage (A 16K + B 16K)
#define GEMM_SMEM (2 * G2STAGE)          // 65536 bytes

template <bool HALF_OUT, bool ROPE>
__global__ __launch_bounds__(128) void gemm_h(const __half* __restrict__ A,
                                              const __half* __restrict__ Bt,
                                              void* __restrict__ Cv,
                                              int M, int N, int K) {
    extern __shared__ char smraw[];
    const unsigned sb = (unsigned)__cvta_generic_to_shared(smraw);

    const int tid = threadIdx.x;
    const int wid = tid >> 5, lane = tid & 31;
    const int g = lane >> 2, t = lane & 3;
    const int j = lane & 7, s1 = (lane >> 3) & 1, s2 = (lane >> 4) & 1;
    const int warp_m = (wid >> 1) * 64;
    const int warp_n = (wid & 1) * 64;
    const int bx = blockIdx.x, by = blockIdx.y;

    // ldmatrix lane bases (bytes); chunk xor constants
    const unsigned a_base = (unsigned)((warp_m + s1 * 8 + j) * 128);
    const unsigned b_base = 16384u + (unsigned)((warp_n + s2 * 8 + j) * 128);
    const unsigned cxa = (unsigned)(s2 ^ j);
    const unsigned cxb = (unsigned)(s1 ^ j);

    // cp.async mapping: 8 A chunks + 8 B chunks per thread per stage
    const int lr = tid >> 3;             // 0..15
    const int c8 = tid & 7;              // 16B chunk in 128B row
    const unsigned lcx = (unsigned)(c8 ^ (lr & 7)) << 4;

    const int nst = K / 64;

    float acc[4][8][4];
#pragma unroll
    for (int i = 0; i < 4; i++)
#pragma unroll
        for (int jj = 0; jj < 8; jj++)
#pragma unroll
            for (int k = 0; k < 4; k++) acc[i][jj][k] = 0.f;

#define GLOAD(kt_) do {                                                          \
        const unsigned _tb = sb + ((kt_) & 1) * G2STAGE;                         \
        const int _ko = (kt_) * 64;                                              \
        _Pragma("unroll")                                                        \
        for (int p = 0; p < 8; p++) {                                            \
            const int r = lr + p * 16;                                           \
            CPA16(_tb + r * 128 + lcx, A + (size_t)(by * 128 + r) * K + _ko + c8 * 8); \
        }                                                                        \
        _Pragma("unroll")                                                        \
        for (int p = 0; p < 8; p++) {                                            \
            const int r = lr + p * 16;                                           \
            CPA16(_tb + 16384 + r * 128 + lcx, Bt + (size_t)(bx * 128 + r) * K + _ko + c8 * 8); \
        }                                                                        \
        CPA_COMMIT();                                                            \
    } while (0)

    GLOAD(0);

    for (int kt = 0; kt < nst; kt++) {
        CPA_WAIT(0);
        __syncthreads();
        if (kt + 1 < nst) GLOAD(kt + 1);

        const unsigned stg = sb + (kt & 1) * G2STAGE;
#pragma unroll
        for (int kk = 0; kk < 4; kk++) {
            unsigned af[4][4], bf[4][4];
#pragma unroll
            for (int mt = 0; mt < 4; mt++)
                LDM4(af[mt], stg + a_base + mt * 2048 + (((2u * kk) ^ cxa) << 4));
#pragma unroll
            for (int np = 0; np < 4; np++)
                LDM4(bf[np], stg + b_base + np * 2048 + (((2u * kk) ^ cxb) << 4));
#pragma unroll
            for (int mt = 0; mt < 4; mt++)
#pragma unroll
                for (int np = 0; np < 4; np++) {
                    mma16(acc[mt][np * 2],     af[mt], bf[np][0], bf[np][1]);
                    mma16(acc[mt][np * 2 + 1], af[mt], bf[np][2], bf[np][3]);
                }
        }
    }
#undef GLOAD

#pragma unroll
    for (int mt = 0; mt < 4; mt++) {
#pragma unroll
        for (int nt = 0; nt < 8; nt++) {
            const int r0 = by * 128 + warp_m + mt * 16 + g;
            const int c0 = bx * 128 + warp_n + nt * 8 + 2 * t;
            float v0 = acc[mt][nt][0], v1 = acc[mt][nt][1];
            float v2 = acc[mt][nt][2], v3 = acc[mt][nt][3];
            if (ROPE && c0 < 2560) {
                const int i = (c0 & 127) >> 1;
                float2 csA = g_rtab[(r0 & (T_ - 1)) * 64 + i];
                float2 csB = g_rtab[((r0 + 8) & (T_ - 1)) * 64 + i];
                float e0 = v0 * csA.x - v1 * csA.y;
                float o0 = v0 * csA.y + v1 * csA.x;
                float e1 = v2 * csB.x - v3 * csB.y;
                float o1 = v2 * csB.y + v3 * csB.x;
                v0 = e0; v1 = o0; v2 = e1; v3 = o1;
            }
            if (HALF_OUT) {
                __half* C = (__half*)Cv;
                *(__half2*)&C[(size_t)r0 * N + c0]       = __floats2half2_rn(v0, v1);
                *(__half2*)&C[(size_t)(r0 + 8) * N + c0] = __floats2half2_rn(v2, v3);
            } else {
                float* C = (float*)Cv;
                *(float2*)&C[(size_t)r0 * N + c0]       = make_float2(v0, v1);
                *(float2*)&C[(size_t)(r0 + 8) * N + c0] = make_float2(v2, v3);
            }
        }
    }
}

// ---------------------------------------------------------------------------
// Flash attention (causal, GQA), fp16 mma + ldmatrix, cp.async dbuf.
// 128 threads / 4 warps; q-tile 64 (16 rows/warp); kv-tile 64.
// P in registers; diagonal tile peeled (mask-free main loop);
// ex2.approx softmax with fused scale; vote-skip O rescale.
// smem bytes: Qs[64][272B] @0 | Ks 2x[64][272B] @17408 | Vs 2x[64][256B sw] @52224
// ---------------------------------------------------------------------------
#define FQ_OFF 0u
#define FK_OFF 17408u
#define FV_OFF 52224u
#define FLASH_SMEM 84992

__global__ __launch_bounds__(128, 2) void flash_h(const __half* __restrict__ qkv,
                                                  __half* __restrict__ y) {
    extern __shared__ char smraw[];
    const unsigned sb = (unsigned)__cvta_generic_to_shared(smraw);

    const int tid = threadIdx.x;
    const int wid = tid >> 5, lane = tid & 31;
    const int g = lane >> 2, t = lane & 3;
    const int j = lane & 7, s1 = (lane >> 3) & 1, s2 = (lane >> 4) & 1;
    const int qb = gridDim.x - 1 - blockIdx.x;   // long blocks first
    const int h = blockIdx.y, b = blockIdx.z;
    const int kvh = h >> 2;
    const int q0 = wid * 16;
    const float SC = 0.08838834764831845f * 1.4426950408889634f;  // scale*log2(e)

    const unsigned q_lane = FQ_OFF + (unsigned)((q0 + s1 * 8 + j) * 272 + s2 * 16);
    const unsigned k_lane = FK_OFF + (unsigned)((s2 * 8 + j) * 272 + s1 * 16);
    const unsigned vrow   = (unsigned)((s1 * 8 + j) * 256);

    const int lrow8 = tid >> 4;          // 0..7
    const int lc = tid & 15;             // 16B chunk within row

    // Q tile (group 0): 64 rows x 16 chunks
#pragma unroll
    for (int it = 0; it < 8; it++) {
        const int row = it * 8 + lrow8;
        CPA16(sb + FQ_OFF + row * 272 + lc * 16,
              qkv + (size_t)(b * T_ + qb * 64 + row) * QKV_DIM + h * DH + lc * 8);
    }
    CPA_COMMIT();

    const int ntiles = qb + 1;

#define KV_LOAD(kt_) do {                                                        \
        const unsigned _stg = (unsigned)((kt_) & 1);                             \
        _Pragma("unroll")                                                        \
        for (int it = 0; it < 8; it++) {                                         \
            const int row = it * 8 + lrow8;                                      \
            const __half* gp = qkv + (size_t)(b * T_ + (kt_) * 64 + row) * QKV_DIM \
                               + D_MODEL + kvh * DH + lc * 8;                    \
            CPA16(sb + FK_OFF + _stg * 17408 + row * 272 + lc * 16, gp);         \
            CPA16(sb + FV_OFF + _stg * 16384 + row * 256 + ((lc ^ (row & 7)) << 4), gp + N_KV * DH); \
        }                                                                        \
        CPA_COMMIT();                                                            \
    } while (0)

    KV_LOAD(0);

    float m_lo = -1e30f, m_hi = -1e30f, l_lo = 0.f, l_hi = 0.f;
    float o[16][4];
#pragma unroll
    for (int i = 0; i < 16; i++)
#pragma unroll
        for (int jj = 0; jj < 4; jj++) o[i][jj] = 0.f;

#define FLASH_TILE(kt_, MASKED) do {                                              \
    if ((kt_) + 1 < ntiles) { KV_LOAD((kt_) + 1); CPA_WAIT(1); }                  \
    else                    { CPA_WAIT(0); }                                      \
    __syncthreads();                                                              \
    const unsigned kstg = ((kt_) & 1) * 17408;                                    \
    const unsigned vstg = FV_OFF + ((kt_) & 1) * 16384;                           \
    float s[8][4];                                                                \
    _Pragma("unroll")                                                             \
    for (int nt = 0; nt < 8; nt++) { s[nt][0]=0.f; s[nt][1]=0.f; s[nt][2]=0.f; s[nt][3]=0.f; } \
    _Pragma("unroll")                                                             \
    for (int kk = 0; kk < 8; kk++) {                                              \
        unsigned a[4];                                                            \
        LDM4(a, sb + q_lane + kk * 32);                                           \
        _Pragma("unroll")                                                         \
        for (int np = 0; np < 4; np++) {                                          \
            unsigned kb[4];                                                       \
            LDM4(kb, sb + k_lane + kstg + np * 4352 + kk * 32);                   \
            mma16(s[np * 2],     a, kb[0], kb[1]);                                \
            mma16(s[np * 2 + 1], a, kb[2], kb[3]);                                \
        }                                                                         \
    }                                                                             \
    float ml = -1e30f, mh = -1e30f;                                               \
    if (MASKED) {                                                                 \
        const int rlo = qb * 64 + q0 + g;                                         \
        const int rhi = rlo + 8;                                                  \
        const int cb = (kt_) * 64;                                                \
        _Pragma("unroll")                                                         \
        for (int nt = 0; nt < 8; nt++) {                                          \
            const int c0 = cb + nt * 8 + 2 * t, c1 = c0 + 1;                      \
            if (c0 > rlo) s[nt][0] = -1e30f;                                      \
            if (c1 > rlo) s[nt][1] = -1e30f;                                      \
            if (c0 > rhi) s[nt][2] = -1e30f;                                      \
            if (c1 > rhi) s[nt][3] = -1e30f;                                      \
        }                                                                         \
    }                                                                             \
    _Pragma("unroll")                                                             \
    for (int nt = 0; nt < 8; nt++) {                                              \
        ml = fmaxf(ml, fmaxf(s[nt][0], s[nt][1]));                                \
        mh = fmaxf(mh, fmaxf(s[nt][2], s[nt][3]));                                \
    }                                                                             \
    ml = fmaxf(ml, __shfl_xor_sync(0xffffffffu, ml, 1));                          \
    ml = fmaxf(ml, __shfl_xor_sync(0xffffffffu, ml, 2));                          \
    mh = fmaxf(mh, __shfl_xor_sync(0xffffffffu, mh, 1));                          \
    mh = fmaxf(mh, __shfl_xor_sync(0xffffffffu, mh, 2));                          \
    const float mnl = fmaxf(m_lo, ml);                                            \
    const float mnh = fmaxf(m_hi, mh);                                            \
    const float nbl = -mnl * SC;                                                  \
    const float nbh = -mnh * SC;                                                  \
    float ll = 0.f, lh = 0.f;                                                     \
    _Pragma("unroll")                                                             \
    for (int nt = 0; nt < 8; nt++) {                                              \
        s[nt][0] = ex2f(fmaf(s[nt][0], SC, nbl));                                 \
        s[nt][1] = ex2f(fmaf(s[nt][1], SC, nbl));                                 \
        s[nt][2] = ex2f(fmaf(s[nt][2], SC, nbh));                                 \
        s[nt][3] = ex2f(fmaf(s[nt][3], SC, nbh));                                 \
        ll += s[nt][0] + s[nt][1];                                                \
        lh += s[nt][2] + s[nt][3];                                                \
    }                                                                             \
    ll += __shfl_xor_sync(0xffffffffu, ll, 1);                                    \
    ll += __shfl_xor_sync(0xffffffffu, ll, 2);                                    \
    lh += __shfl_xor_sync(0xffffffffu, lh, 1);                                    \
    lh += __shfl_xor_sync(0xffffffffu, lh, 2);                                    \
    if (__all_sync(0xffffffffu, (mnl == m_lo) & (mnh == m_hi))) {                 \
        l_lo += ll; l_hi += lh;                                                   \
    } else {                                                                      \
        const float al = ex2f((m_lo - mnl) * SC);                                 \
        const float ah = ex2f((m_hi - mnh) * SC);                                 \
        l_lo = l_lo * al + ll;                                                    \
        l_hi = l_hi * ah + lh;                                                    \
        _Pragma("unroll")                                                         \
        for (int nt = 0; nt < 16; nt++) {                                         \
            o[nt][0] *= al; o[nt][1] *= al;                                       \
            o[nt][2] *= ah; o[nt][3] *= ah;                                       \
        }                                                                         \
    }                                                                             \
    m_lo = mnl; m_hi = mnh;                                                       \
    _Pragma("unroll")                                                             \
    for (int kk = 0; kk < 4; kk++) {                                              \
        unsigned a[4];                                                            \
        a[0] = h2u(__floats2half2_rn(s[2 * kk][0],     s[2 * kk][1]));            \
        a[1] = h2u(__floats2half2_rn(s[2 * kk][2],     s[2 * kk][3]));            \
        a[2] = h2u(__floats2half2_rn(s[2 * kk + 1][0], s[2 * kk + 1][1]));        \
        a[3] = h2u(__floats2half2_rn(s[2 * kk + 1][2], s[2 * kk + 1][3]));        \
        _Pragma("unroll")                                                         \
        for (int np = 0; np < 8; np++) {                                          \
            unsigned vb[4];                                                       \
            const unsigned chunk = (unsigned)(((np << 1) | s2) ^ j);              \
            LDM4T(vb, sb + vstg + kk * 4096 + vrow + (chunk << 4));               \
            mma16(o[np * 2],     a, vb[0], vb[1]);                                \
            mma16(o[np * 2 + 1], a, vb[2], vb[3]);                                \
        }                                                                         \
    }                                                                             \
    __syncthreads();                                                              \
} while (0)

    for (int kt = 0; kt < ntiles - 1; kt++) FLASH_TILE(kt, false);
    FLASH_TILE(ntiles - 1, true);

#undef FLASH_TILE
#undef KV_LOAD

    // epilogue: normalize, write y (fp16)
    const float il = 1.f / l_lo;
    const float ih = 1.f / l_hi;
    const size_t rl = (size_t)(b * T_ + qb * 64 + q0 + g);
#pragma unroll
    for (int nt = 0; nt < 16; nt++) {
        const int c = h * DH + nt * 8 + 2 * t;
        *(__half2*)&y[rl * D_MODEL + c]       = __floats2half2_rn(o[nt][0] * il, o[nt][1] * il);
        *(__half2*)&y[(rl + 8) * D_MODEL + c] = __floats2half2_rn(o[nt][2] * ih, o[nt][3] * ih);
    }
}

// ---------------------------------------------------------------------------
// Launch
// ---------------------------------------------------------------------------
extern "C" void kernel_launch(void* const* d_in, const int* in_sizes, int n_in,
                              void* d_out, int out_size) {
    const float* x        = (const float*)d_in[0];   // (2, 2048, 2048)
    const float* Wqkv     = (const float*)d_in[1];   // (2048, 3072)
    const float* Wo       = (const float*)d_in[2];   // (2048, 2048)
    const int*   startpos = (const int*)d_in[3];     // scalar
    float* out = (float*)d_out;                      // (2, 2048, 2048)

    __half *qkvh, *yh, *xh, *wqT, *woT;
    cudaGetSymbolAddress((void**)&qkvh, g_qkvh);
    cudaGetSymbolAddress((void**)&yh, g_yh);
    cudaGetSymbolAddress((void**)&xh, g_xh);
    cudaGetSymbolAddress((void**)&wqT, g_wqT);
    cudaGetSymbolAddress((void**)&woT, g_woT);

    cudaFuncSetAttribute((void*)gemm_h<true, true>,   cudaFuncAttributeMaxDynamicSharedMemorySize, GEMM_SMEM);
    cudaFuncSetAttribute((void*)gemm_h<false, false>, cudaFuncAttributeMaxDynamicSharedMemorySize, GEMM_SMEM);
    cudaFuncSetAttribute((void*)flash_h, cudaFuncAttributeMaxDynamicSharedMemorySize, FLASH_SMEM);

    // 0) pre-pass: fp16 conversions + weight transposes + rope table
    conv_h_kernel<<<(ROWS * D_MODEL / 4 + 255) / 256, 256>>>(x, (__half2*)xh, ROWS * D_MODEL / 4);
    transpose_h_kernel<<<dim3(QKV_DIM / 32, D_MODEL / 32), dim3(32, 8)>>>(Wqkv, wqT, D_MODEL, QKV_DIM);
    transpose_h_kernel<<<dim3(D_MODEL / 32, D_MODEL / 32), dim3(32, 8)>>>(Wo, woT, D_MODEL, D_MODEL);
    rope_table_kernel<<<T_ * 64 / 256, 256>>>(startpos);

    // 1) qkv = x @ Wqkv with fused RoPE (fp16 out)
    dim3 g1(QKV_DIM / 128, ROWS / 128);
    gemm_h<true, true><<<g1, 128, GEMM_SMEM>>>(xh, wqT, qkvh, ROWS, QKV_DIM, D_MODEL);

    // 2) flash attention -> yh (fp16)
    dim3 g3(T_ / 64, N_HEADS, B_);
    flash_h<<<g3, 128, FLASH_SMEM>>>(qkvh, yh);

    // 3) out = y @ Wo  (fp32 out)
    dim3 g4(D_MODEL / 128, ROWS / 128);
    gemm_h<false, false><<<g4, 128, GEMM_SMEM>>>(yh, woT, out, ROWS, D_MODEL, D_MODEL);
}

// round 12
// speedup vs baseline: 28.7697x; 1.0098x over previous
#include <cuda_runtime.h>
#include <cuda_fp16.h>
#include <math_constants.h>
#include <cstdint>

// Problem constants
#define D_MODEL   2048
#define N_HEADS   16
#define N_KV      4
#define DH        128
#define B_        2
#define T_        2048
#define QKV_DIM   3072          // 2048 + 2*4*128
#define ROWS      (B_*T_)       // 4096

// Scratch (static device allocations only)
__device__ __half  g_qkvh[ROWS * QKV_DIM];      // 24 MB
__device__ __half  g_yh  [ROWS * D_MODEL];      // 16 MB
__device__ __half  g_xh  [ROWS * D_MODEL];      // 16 MB  (fp16 x)
__device__ __half  g_wqT [QKV_DIM * D_MODEL];   // 12 MB  (fp16 Wqkv^T  [N][K])
__device__ __half  g_woT [D_MODEL * D_MODEL];   //  8 MB  (fp16 Wo^T    [N][K])
__device__ float2  g_rtab[T_ * 64];             //  1 MB  (cos/sin table)

// ---------------------------------------------------------------------------
// helpers
// ---------------------------------------------------------------------------
__device__ __forceinline__ void mma16(float c[4], const unsigned a[4],
                                      unsigned b0, unsigned b1) {
    asm volatile(
        "mma.sync.aligned.m16n8k16.row.col.f32.f16.f16.f32 "
        "{%0,%1,%2,%3},{%4,%5,%6,%7},{%8,%9},{%0,%1,%2,%3};"
        : "+f"(c[0]), "+f"(c[1]), "+f"(c[2]), "+f"(c[3])
        : "r"(a[0]), "r"(a[1]), "r"(a[2]), "r"(a[3]), "r"(b0), "r"(b1));
}

#define LDM4(d, addr) \
    asm volatile("ldmatrix.sync.aligned.m8n8.x4.shared.b16 {%0,%1,%2,%3}, [%4];" \
        : "=r"((d)[0]), "=r"((d)[1]), "=r"((d)[2]), "=r"((d)[3]) : "r"(addr))
#define LDM4T(d, addr) \
    asm volatile("ldmatrix.sync.aligned.m8n8.x4.trans.shared.b16 {%0,%1,%2,%3}, [%4];" \
        : "=r"((d)[0]), "=r"((d)[1]), "=r"((d)[2]), "=r"((d)[3]) : "r"(addr))

#define CPA16(dst_u32, src_ptr) \
    asm volatile("cp.async.cg.shared.global [%0], [%1], 16;" :: "r"(dst_u32), "l"(src_ptr))
#define CPA_COMMIT() asm volatile("cp.async.commit_group;")
#define CPA_WAIT(n)  asm volatile("cp.async.wait_group %0;" :: "n"(n))

__device__ __forceinline__ unsigned h2u(__half2 h) { return *(unsigned*)&h; }
__device__ __forceinline__ float ex2f(float x) {
    float r;
    asm("ex2.approx.ftz.f32 %0, %1;" : "=f"(r) : "f"(x));
    return r;
}

// ---------------------------------------------------------------------------
// pre-pass: fp32 -> fp16 conversion of x
// ---------------------------------------------------------------------------
__global__ __launch_bounds__(256) void conv_h_kernel(const float* __restrict__ in,
                                                     __half2* __restrict__ out, int n4) {
    int i = blockIdx.x * 256 + threadIdx.x;
    if (i >= n4) return;
    float4 v = ((const float4*)in)[i];
    out[2 * i]     = __floats2half2_rn(v.x, v.y);
    out[2 * i + 1] = __floats2half2_rn(v.z, v.w);
}

// ---------------------------------------------------------------------------
// pre-pass: transpose + convert weights: W[K][N] fp32 -> WT[N][K] fp16
// 64 k-rows x 32 n-cols per block; 128B coalesced reads and half2 writes.
// ---------------------------------------------------------------------------
__global__ __launch_bounds__(256) void transpose_h_kernel(const float* __restrict__ in,
                                                          __half* __restrict__ out,
                                                          int K, int N) {
    __shared__ float tile[64][33];
    const int tx = threadIdx.x, ty = threadIdx.y;   // 32 x 8
    const int n0 = blockIdx.x * 32, k0 = blockIdx.y * 64;
#pragma unroll
    for (int jj = 0; jj < 8; jj++)
        tile[ty + 8 * jj][tx] = in[(size_t)(k0 + ty + 8 * jj) * N + n0 + tx];
    __syncthreads();
#pragma unroll
    for (int it = 0; it < 4; it++) {
        const int r = ty + 8 * it;                  // out row within n-tile
        __half2 h = __floats2half2_rn(tile[2 * tx][r], tile[2 * tx + 1][r]);
        *(__half2*)&out[(size_t)(n0 + r) * K + k0 + 2 * tx] = h;
    }
}

// ---------------------------------------------------------------------------
// rope table: cos/sin for (t, i)
// ---------------------------------------------------------------------------
__global__ __launch_bounds__(256) void rope_table_kernel(const int* __restrict__ start_pos) {
    int id = blockIdx.x * 256 + threadIdx.x;    // < 2048*64
    int t = id >> 6, i = id & 63;
    float pos = (float)(start_pos[0] + t);
    float inv = exp2f(-(float)i * (13.287712379549449f / 64.0f));
    float ang = pos * inv;
    float s, c;
    sincosf(ang, &s, &c);
    g_rtab[id] = make_float2(c, s);
}

// ---------------------------------------------------------------------------
// fp16 GEMM: C[M,N] = A[M,K] @ BT[N][K]^T; fp32 accum.
// 128x128 CTA tile, 128 threads (4 warps, 64x64 warp tile), BK=64,
// 128B swizzled smem rows, cp.async THREE-stage pipeline, ldmatrix frags.
// ROPE: rotary embedding fused into epilogue for columns < 2560 (q,k regions).
// ---------------------------------------------------------------------------
#define G3STAGE 32768                    // bytes per stage (A 16K + B 16K)
#define GEMM_SMEM (3 * G3STAGE)          // 98304 bytes

template <bool HALF_OUT, bool ROPE>
__global__ __launch_bounds__(128) void gemm_h(const __half* __restrict__ A,
                                              const __half* __restrict__ Bt,
                                              void* __restrict__ Cv,
                                              int M, int N, int K) {
    extern __shared__ char smraw[];
    const unsigned sb = (unsigned)__cvta_generic_to_shared(smraw);

    const int tid = threadIdx.x;
    const int wid = tid >> 5, lane = tid & 31;
    const int g = lane >> 2, t = lane & 3;
    const int j = lane & 7, s1 = (lane >> 3) & 1, s2 = (lane >> 4) & 1;
    const int warp_m = (wid >> 1) * 64;
    const int warp_n = (wid & 1) * 64;
    const int bx = blockIdx.x, by = blockIdx.y;

    // ldmatrix lane bases (bytes); chunk xor constants
    const unsigned a_base = (unsigned)((warp_m + s1 * 8 + j) * 128);
    const unsigned b_base = 16384u + (unsigned)((warp_n + s2 * 8 + j) * 128);
    const unsigned cxa = (unsigned)(s2 ^ j);
    const unsigned cxb = (unsigned)(s1 ^ j);

    // cp.async mapping: 8 A chunks + 8 B chunks per thread per stage
    const int lr = tid >> 3;             // 0..15
    const int c8 = tid & 7;              // 16B chunk in 128B row
    const unsigned lcx = (unsigned)(c8 ^ (lr & 7)) << 4;

    const int nst = K / 64;

    float acc[4][8][4];
#pragma unroll
    for (int i = 0; i < 4; i++)
#pragma unroll
        for (int jj = 0; jj < 8; jj++)
#pragma unroll
            for (int k = 0; k < 4; k++) acc[i][jj][k] = 0.f;

#define GLOAD(kt_) do {                                                          \
        const unsigned _tb = sb + ((kt_) % 3) * G3STAGE;                         \
        const int _ko = (kt_) * 64;                                              \
        _Pragma("unroll")                                                        \
        for (int p = 0; p < 8; p++) {                                            \
            const int r = lr + p * 16;                                           \
            CPA16(_tb + r * 128 + lcx, A + (size_t)(by * 128 + r) * K + _ko + c8 * 8); \
        }                                                                        \
        _Pragma("unroll")                                                        \
        for (int p = 0; p < 8; p++) {                                            \
            const int r = lr + p * 16;                                           \
            CPA16(_tb + 16384 + r * 128 + lcx, Bt + (size_t)(bx * 128 + r) * K + _ko + c8 * 8); \
        }                                                                        \
        CPA_COMMIT();                                                            \
    } while (0)

    GLOAD(0);
    GLOAD(1);

    for (int kt = 0; kt < nst; kt++) {
        CPA_WAIT(1);                     // stage kt landed (kt+1 may be in flight)
        __syncthreads();                 // everyone done with stage kt-1 & past wait
        if (kt + 2 < nst) GLOAD(kt + 2); // its stage (== kt-1's slot) is now free

        const unsigned stg = sb + (kt % 3) * G3STAGE;
#pragma unroll
        for (int kk = 0; kk < 4; kk++) {
            unsigned af[4][4], bf[4][4];
#pragma unroll
            for (int mt = 0; mt < 4; mt++)
                LDM4(af[mt], stg + a_base + mt * 2048 + (((2u * kk) ^ cxa) << 4));
#pragma unroll
            for (int np = 0; np < 4; np++)
                LDM4(bf[np], stg + b_base + np * 2048 + (((2u * kk) ^ cxb) << 4));
#pragma unroll
            for (int mt = 0; mt < 4; mt++)
#pragma unroll
                for (int np = 0; np < 4; np++) {
                    mma16(acc[mt][np * 2],     af[mt], bf[np][0], bf[np][1]);
                    mma16(acc[mt][np * 2 + 1], af[mt], bf[np][2], bf[np][3]);
                }
        }
    }
#undef GLOAD

#pragma unroll
    for (int mt = 0; mt < 4; mt++) {
#pragma unroll
        for (int nt = 0; nt < 8; nt++) {
            const int r0 = by * 128 + warp_m + mt * 16 + g;
            const int c0 = bx * 128 + warp_n + nt * 8 + 2 * t;
            float v0 = acc[mt][nt][0], v1 = acc[mt][nt][1];
            float v2 = acc[mt][nt][2], v3 = acc[mt][nt][3];
            if (ROPE && c0 < 2560) {
                const int i = (c0 & 127) >> 1;
                float2 csA = g_rtab[(r0 & (T_ - 1)) * 64 + i];
                float2 csB = g_rtab[((r0 + 8) & (T_ - 1)) * 64 + i];
                float e0 = v0 * csA.x - v1 * csA.y;
                float o0 = v0 * csA.y + v1 * csA.x;
                float e1 = v2 * csB.x - v3 * csB.y;
                float o1 = v2 * csB.y + v3 * csB.x;
                v0 = e0; v1 = o0; v2 = e1; v3 = o1;
            }
            if (HALF_OUT) {
                __half* C = (__half*)Cv;
                *(__half2*)&C[(size_t)r0 * N + c0]       = __floats2half2_rn(v0, v1);
                *(__half2*)&C[(size_t)(r0 + 8) * N + c0] = __floats2half2_rn(v2, v3);
            } else {
                float* C = (float*)Cv;
                *(float2*)&C[(size_t)r0 * N + c0]       = make_float2(v0, v1);
                *(float2*)&C[(size_t)(r0 + 8) * N + c0] = make_float2(v2, v3);
            }
        }
    }
}

// ---------------------------------------------------------------------------
// Flash attention (causal, GQA), fp16 mma + ldmatrix, cp.async dbuf.
// 128 threads / 4 warps; q-tile 64 (16 rows/warp); kv-tile 64.
// Q fragments hoisted to registers; P in registers; diagonal tile peeled;
// ex2.approx softmax with fused scale; vote-skip O rescale.
// smem bytes: Qs[64][272B] @0 | Ks 2x[64][272B] @17408 | Vs 2x[64][256B sw] @52224
// ---------------------------------------------------------------------------
#define FQ_OFF 0u
#define FK_OFF 17408u
#define FV_OFF 52224u
#define FLASH_SMEM 84992

__global__ __launch_bounds__(128, 2) void flash_h(const __half* __restrict__ qkv,
                                                  __half* __restrict__ y) {
    extern __shared__ char smraw[];
    const unsigned sb = (unsigned)__cvta_generic_to_shared(smraw);

    const int tid = threadIdx.x;
    const int wid = tid >> 5, lane = tid & 31;
    const int g = lane >> 2, t = lane & 3;
    const int j = lane & 7, s1 = (lane >> 3) & 1, s2 = (lane >> 4) & 1;
    const int qb = gridDim.x - 1 - blockIdx.x;   // long blocks first
    const int h = blockIdx.y, b = blockIdx.z;
    const int kvh = h >> 2;
    const int q0 = wid * 16;
    const float SC = 0.08838834764831845f * 1.4426950408889634f;  // scale*log2(e)

    const unsigned q_lane = FQ_OFF + (unsigned)((q0 + s1 * 8 + j) * 272 + s2 * 16);
    const unsigned k_lane = FK_OFF + (unsigned)((s2 * 8 + j) * 272 + s1 * 16);
    const unsigned vrow   = (unsigned)((s1 * 8 + j) * 256);

    const int lrow8 = tid >> 4;          // 0..7
    const int lc = tid & 15;             // 16B chunk within row

    // Q tile (group A): 64 rows x 16 chunks
#pragma unroll
    for (int it = 0; it < 8; it++) {
        const int row = it * 8 + lrow8;
        CPA16(sb + FQ_OFF + row * 272 + lc * 16,
              qkv + (size_t)(b * T_ + qb * 64 + row) * QKV_DIM + h * DH + lc * 8);
    }
    CPA_COMMIT();

    const int ntiles = qb + 1;

#define KV_LOAD(kt_) do {                                                        \
        const unsigned _stg = (unsigned)((kt_) & 1);                             \
        _Pragma("unroll")                                                        \
        for (int it = 0; it < 8; it++) {                                         \
            const int row = it * 8 + lrow8;                                      \
            const __half* gp = qkv + (size_t)(b * T_ + (kt_) * 64 + row) * QKV_DIM \
                               + D_MODEL + kvh * DH + lc * 8;                    \
            CPA16(sb + FK_OFF + _stg * 17408 + row * 272 + lc * 16, gp);         \
            CPA16(sb + FV_OFF + _stg * 16384 + row * 256 + ((lc ^ (row & 7)) << 4), gp + N_KV * DH); \
        }                                                                        \
        CPA_COMMIT();                                                            \
    } while (0)

    KV_LOAD(0);

    // hoist Q fragments to registers (Q group done once <=1 group pending)
    unsigned qf[8][4];
    CPA_WAIT(1);
    __syncthreads();
#pragma unroll
    for (int kk = 0; kk < 8; kk++)
        LDM4(qf[kk], sb + q_lane + kk * 32);

    float m_lo = -1e30f, m_hi = -1e30f, l_lo = 0.f, l_hi = 0.f;
    float o[16][4];
#pragma unroll
    for (int i = 0; i < 16; i++)
#pragma unroll
        for (int jj = 0; jj < 4; jj++) o[i][jj] = 0.f;

#define FLASH_TILE(kt_, MASKED) do {                                              \
    if ((kt_) + 1 < ntiles) { KV_LOAD((kt_) + 1); CPA_WAIT(1); }                  \
    else                    { CPA_WAIT(0); }                                      \
    __syncthreads();                                                              \
    const unsigned kstg = ((kt_) & 1) * 17408;                                    \
    const unsigned vstg = FV_OFF + ((kt_) & 1) * 16384;                           \
    float s[8][4];                                                                \
    _Pragma("unroll")                                                             \
    for (int nt = 0; nt < 8; nt++) { s[nt][0]=0.f; s[nt][1]=0.f; s[nt][2]=0.f; s[nt][3]=0.f; } \
    _Pragma("unroll")                                                             \
    for (int kk = 0; kk < 8; kk++) {                                              \
        _Pragma("unroll")                                                         \
        for (int np = 0; np < 4; np++) {                                          \
            unsigned kb[4];                                                       \
            LDM4(kb, sb + k_lane + kstg + np * 4352 + kk * 32);                   \
            mma16(s[np * 2],     qf[kk], kb[0], kb[1]);                           \
            mma16(s[np * 2 + 1], qf[kk], kb[2], kb[3]);                           \
        }                                                                         \
    }                                                                             \
    float ml = -1e30f, mh = -1e30f;                                               \
    if (MASKED) {                                                                 \
        const int rlo = qb * 64 + q0 + g;                                         \
        const int rhi = rlo + 8;                                                  \
        const int cb = (kt_) * 64;                                                \
        _Pragma("unroll")                                                         \
        for (int nt = 0; nt < 8; nt++) {                                          \
            const int c0 = cb + nt * 8 + 2 * t, c1 = c0 + 1;                      \
            if (c0 > rlo) s[nt][0] = -1e30f;                                      \
            if (c1 > rlo) s[nt][1] = -1e30f;                                      \
            if (c0 > rhi) s[nt][2] = -1e30f;                                      \
            if (c1 > rhi) s[nt][3] = -1e30f;                                      \
        }                                                                         \
    }                                                                             \
    _Pragma("unroll")                                                             \
    for (int nt = 0; nt < 8; nt++) {                                              \
        ml = fmaxf(ml, fmaxf(s[nt][0], s[nt][1]));                                \
        mh = fmaxf(mh, fmaxf(s[nt][2], s[nt][3]));                                \
    }                                                                             \
    ml = fmaxf(ml, __shfl_xor_sync(0xffffffffu, ml, 1));                          \
    ml = fmaxf(ml, __shfl_xor_sync(0xffffffffu, ml, 2));                          \
    mh = fmaxf(mh, __shfl_xor_sync(0xffffffffu, mh, 1));                          \
    mh = fmaxf(mh, __shfl_xor_sync(0xffffffffu, mh, 2));                          \
    const float mnl = fmaxf(m_lo, ml);                                            \
    const float mnh = fmaxf(m_hi, mh);                                            \
    const float nbl = -mnl * SC;                                                  \
    const float nbh = -mnh * SC;                                                  \
    float ll = 0.f, lh = 0.f;                                                     \
    _Pragma("unroll")                                                             \
    for (int nt = 0; nt < 8; nt++) {                                              \
        s[nt][0] = ex2f(fmaf(s[nt][0], SC, nbl));                                 \
        s[nt][1] = ex2f(fmaf(s[nt][1], SC, nbl));                                 \
        s[nt][2] = ex2f(fmaf(s[nt][2], SC, nbh));                                 \
        s[nt][3] = ex2f(fmaf(s[nt][3], SC, nbh));                                 \
        ll += s[nt][0] + s[nt][1];                                                \
        lh += s[nt][2] + s[nt][3];                                                \
    }                                                                             \
    ll += __shfl_xor_sync(0xffffffffu, ll, 1);                                    \
    ll += __shfl_xor_sync(0xffffffffu, ll, 2);                                    \
    lh += __shfl_xor_sync(0xffffffffu, lh, 1);                                    \
    lh += __shfl_xor_sync(0xffffffffu, lh, 2);                                    \
    if (__all_sync(0xffffffffu, (mnl == m_lo) & (mnh == m_hi))) {                 \
        l_lo += ll; l_hi += lh;                                                   \
    } else {                                                                      \
        const float al = ex2f((m_lo - mnl) * SC);                                 \
        const float ah = ex2f((m_hi - mnh) * SC);                                 \
        l_lo = l_lo * al + ll;                                                    \
        l_hi = l_hi * ah + lh;                                                    \
        _Pragma("unroll")                                                         \
        for (int nt = 0; nt < 16; nt++) {                                         \
            o[nt][0] *= al; o[nt][1] *= al;                                       \
            o[nt][2] *= ah; o[nt][3] *= ah;                                       \
        }                                                                         \
    }                                                                             \
    m_lo = mnl; m_hi = mnh;                                                       \
    _Pragma("unroll")                                                             \
    for (int kk = 0; kk < 4; kk++) {                                              \
        unsigned a[4];                                                            \
        a[0] = h2u(__floats2half2_rn(s[2 * kk][0],     s[2 * kk][1]));            \
        a[1] = h2u(__floats2half2_rn(s[2 * kk][2],     s[2 * kk][3]));            \
        a[2] = h2u(__floats2half2_rn(s[2 * kk + 1][0], s[2 * kk + 1][1]));        \
        a[3] = h2u(__floats2half2_rn(s[2 * kk + 1][2], s[2 * kk + 1][3]));        \
        _Pragma("unroll")                                                         \
        for (int np = 0; np < 8; np++) {                                          \
            unsigned vb[4];                                                       \
            const unsigned chunk = (unsigned)(((np << 1) | s2) ^ j);              \
            LDM4T(vb, sb + vstg + kk * 4096 + vrow + (chunk << 4));               \
            mma16(o[np * 2],     a, vb[0], vb[1]);                                \
            mma16(o[np * 2 + 1], a, vb[2], vb[3]);                                \
        }                                                                         \
    }                                                                             \
    __syncthreads();                                                              \
} while (0)

    for (int kt = 0; kt < ntiles - 1; kt++) FLASH_TILE(kt, false);
    FLASH_TILE(ntiles - 1, true);

#undef FLASH_TILE
#undef KV_LOAD

    // epilogue: normalize, write y (fp16)
    const float il = 1.f / l_lo;
    const float ih = 1.f / l_hi;
    const size_t rl = (size_t)(b * T_ + qb * 64 + q0 + g);
#pragma unroll
    for (int nt = 0; nt < 16; nt++) {
        const int c = h * DH + nt * 8 + 2 * t;
        *(__half2*)&y[rl * D_MODEL + c]       = __floats2half2_rn(o[nt][0] * il, o[nt][1] * il);
        *(__half2*)&y[(rl + 8) * D_MODEL + c] = __floats2half2_rn(o[nt][2] * ih, o[nt][3] * ih);
    }
}

// ---------------------------------------------------------------------------
// Launch
// ---------------------------------------------------------------------------
extern "C" void kernel_launch(void* const* d_in, const int* in_sizes, int n_in,
                              void* d_out, int out_size) {
    const float* x        = (const float*)d_in[0];   // (2, 2048, 2048)
    const float* Wqkv     = (const float*)d_in[1];   // (2048, 3072)
    const float* Wo       = (const float*)d_in[2];   // (2048, 2048)
    const int*   startpos = (const int*)d_in[3];     // scalar
    float* out = (float*)d_out;                      // (2, 2048, 2048)

    __half *qkvh, *yh, *xh, *wqT, *woT;
    cudaGetSymbolAddress((void**)&qkvh, g_qkvh);
    cudaGetSymbolAddress((void**)&yh, g_yh);
    cudaGetSymbolAddress((void**)&xh, g_xh);
    cudaGetSymbolAddress((void**)&wqT, g_wqT);
    cudaGetSymbolAddress((void**)&woT, g_woT);

    cudaFuncSetAttribute((void*)gemm_h<true, true>,   cudaFuncAttributeMaxDynamicSharedMemorySize, GEMM_SMEM);
    cudaFuncSetAttribute((void*)gemm_h<false, false>, cudaFuncAttributeMaxDynamicSharedMemorySize, GEMM_SMEM);
    cudaFuncSetAttribute((void*)flash_h, cudaFuncAttributeMaxDynamicSharedMemorySize, FLASH_SMEM);

    // 0) pre-pass: fp16 conversions + weight transposes + rope table
    conv_h_kernel<<<(ROWS * D_MODEL / 4 + 255) / 256, 256>>>(x, (__half2*)xh, ROWS * D_MODEL / 4);
    transpose_h_kernel<<<dim3(QKV_DIM / 32, D_MODEL / 64), dim3(32, 8)>>>(Wqkv, wqT, D_MODEL, QKV_DIM);
    transpose_h_kernel<<<dim3(D_MODEL / 32, D_MODEL / 64), dim3(32, 8)>>>(Wo, woT, D_MODEL, D_MODEL);
    rope_table_kernel<<<T_ * 64 / 256, 256>>>(startpos);

    // 1) qkv = x @ Wqkv with fused RoPE (fp16 out)
    dim3 g1(QKV_DIM / 128, ROWS / 128);
    gemm_h<true, true><<<g1, 128, GEMM_SMEM>>>(xh, wqT, qkvh, ROWS, QKV_DIM, D_MODEL);

    // 2) flash attention -> yh (fp16)
    dim3 g3(T_ / 64, N_HEADS, B_);
    flash_h<<<g3, 128, FLASH_SMEM>>>(qkvh, yh);

    // 3) out = y @ Wo  (fp32 out)
    dim3 g4(D_MODEL / 128, ROWS / 128);
    gemm_h<false, false><<<g4, 128, GEMM_SMEM>>>(yh, woT, out, ROWS, D_MODEL, D_MODEL);
}